// round 9
// baseline (speedup 1.0000x reference)
#include <cuda_runtime.h>
#include <cstdint>
#include <math.h>

#define B_ 16
#define R_ 1024
#define F_ 128
#define D_ 128
#define K_ 7
#define H_ 512
#define H2_ 256
#define FEAT_ 263   // 2*D + K
#define NB1_ 32     // k1 blocks per batch (32 rows each)
#define NB3_ 32     // k3 blocks per batch (32 rows each)

// ---------------- device scratch (static, allocation-free) ----------------
__device__ float E_g[B_ * R_ * F_];          // exp(masked S)
__device__ float Zrow_g[B_ * R_];            // sum_f E*mexf
__device__ float pscore_g[B_ * R_];          // S.sum(f) * pm
__device__ float Zcolp_g[B_ * NB1_ * F_];    // partial: sum_r E*mexr
__device__ float ligcolp_g[B_ * NB1_ * F_];  // partial: sum_r S
__device__ float abarp_g[B_ * NB1_ * F_];    // partial: sum_r coef_r*E
__device__ float tstrp_g[B_ * NB1_ * 8];     // partial type strength
__device__ float Pwp_g[B_ * NB3_ * D_];      // partial: sum_r pscore_r*P  (unscaled)
__device__ float Cwp_g[B_ * NB3_ * D_];      // partial: sum_r craw_r*P    (unscaled)

// ---------------- helpers ----------------
__device__ __forceinline__ float warpSum(float v) {
    #pragma unroll
    for (int o = 16; o > 0; o >>= 1) v += __shfl_down_sync(0xffffffffu, v, o);
    return v;
}
__device__ __forceinline__ float warpAllSum(float v) {
    #pragma unroll
    for (int o = 16; o > 0; o >>= 1) v += __shfl_xor_sync(0xffffffffu, v, o);
    return v;
}
__device__ __forceinline__ float blockReduceSum(float v, float* sm) {
    int lane = threadIdx.x & 31, w = threadIdx.x >> 5;
    int nw = (blockDim.x + 31) >> 5;
    v = warpSum(v);
    if (lane == 0) sm[w] = v;
    __syncthreads();
    float r = (threadIdx.x < nw) ? sm[threadIdx.x] : 0.0f;
    if (w == 0) r = warpSum(r);
    if (threadIdx.x == 0) sm[0] = r;
    __syncthreads();
    r = sm[0];
    __syncthreads();
    return r;
}
__device__ __forceinline__ void l2pf(const void* p) {
    asm volatile("prefetch.global.L2 [%0];" :: "l"(p));
}

// ============ K1: logits pass — lean softmax (no max, deferred weights) ====
__global__ void __launch_bounds__(256, 4) k1_logits(const float* __restrict__ logits,
                          const float* __restrict__ fg_mask,
                          const float* __restrict__ prot_mask,
                          const float* __restrict__ tw) {
    int b = blockIdx.y, blk = blockIdx.x;
    int tid = threadIdx.x, w = tid >> 5, t = tid & 31;

    __shared__ float buf[8 * 896];     // 28KB: 8 logits rows / staging
    __shared__ float tks[8][8];
    __shared__ float wsh_s[8];

    if (tid < K_) {
        float x = tw[tid];
        wsh_s[tid] = fmaxf(x, 0.0f) + log1pf(expf(-fabsf(x)));
    }
    __syncthreads();
    float wshr[K_];
    #pragma unroll
    for (int k = 0; k < K_; k++) wshr[k] = wsh_s[k];

    float fgc[4], mexfc[4];
    #pragma unroll
    for (int c = 0; c < 4; c++) {
        fgc[c] = fg_mask[b * F_ + t + 32 * c];
        mexfc[c] = __expf(-(1.0f - fgc[c]) * 1e9f);
    }

    float zc[4] = {0,0,0,0}, lc[4] = {0,0,0,0}, ab[4] = {0,0,0,0};
    float tk[K_];
    #pragma unroll
    for (int k = 0; k < K_; k++) tk[k] = 0.0f;

    int r0 = blk * 32;
    for (int tile = 0; tile < 4; tile++) {
        const float4* src = (const float4*)(logits + (size_t)(b * R_ + r0 + tile * 8) * 896);
        __syncthreads();
        #pragma unroll
        for (int i = 0; i < 7; i++) ((float4*)buf)[tid + 256 * i] = src[tid + 256 * i];
        __syncthreads();

        int r = r0 + tile * 8 + w;
        float pm = prot_mask[b * R_ + r];
        float mexr = __expf(-(1.0f - pm) * 1e9f);
        float pmf[4];
        #pragma unroll
        for (int c = 0; c < 4; c++) pmf[c] = pm * fgc[c];
        float rowS = 0.0f, rowE = 0.0f;
        float Ev[4];

        #pragma unroll
        for (int c = 0; c < 4; c++) {
            int fb = w * 896 + (t + 32 * c) * 7;     // lane stride 7: conflict-free
            // softmax over K without max subtraction (logits ~ N(0,1), safe)
            float e0 = __expf(buf[fb+0]);
            float e1 = __expf(buf[fb+1]);
            float e2 = __expf(buf[fb+2]);
            float e3 = __expf(buf[fb+3]);
            float e4 = __expf(buf[fb+4]);
            float e5 = __expf(buf[fb+5]);
            float e6 = __expf(buf[fb+6]);
            float s = ((e0+e1)+(e2+e3)) + ((e4+e5)+e6);
            float inv = __fdividef(1.0f, s);
            // weighted numerator in one FFMA chain
            float h = e0*wshr[0];
            h = fmaf(e1, wshr[1], h);
            h = fmaf(e2, wshr[2], h);
            h = fmaf(e3, wshr[3], h);
            h = fmaf(e4, wshr[4], h);
            h = fmaf(e5, wshr[5], h);
            h = fmaf(e6, wshr[6], h);
            // type-strength: accumulate e_k*inv, scale by w_k once at block end
            tk[0] = fmaf(e0, inv, tk[0]);
            tk[1] = fmaf(e1, inv, tk[1]);
            tk[2] = fmaf(e2, inv, tk[2]);
            tk[3] = fmaf(e3, inv, tk[3]);
            tk[4] = fmaf(e4, inv, tk[4]);
            tk[5] = fmaf(e5, inv, tk[5]);
            tk[6] = fmaf(e6, inv, tk[6]);
            float Sm = h * inv * pmf[c];
            float E = __expf(Sm);
            E_g[(size_t)(b * R_ + r) * F_ + t + 32 * c] = E;
            Ev[c] = E;
            rowS += Sm;
            rowE = fmaf(E, mexfc[c], rowE);
            zc[c] = fmaf(E, mexr, zc[c]);
            lc[c] += Sm;
        }
        rowS = warpAllSum(rowS);
        rowE = warpAllSum(rowE);
        float ps = rowS * pm;
        if (t == 0) { pscore_g[b * R_ + r] = ps; Zrow_g[b * R_ + r] = rowE; }
        float coef = __fdividef(ps, rowE);
        #pragma unroll
        for (int c = 0; c < 4; c++) ab[c] = fmaf(coef, Ev[c], ab[c]);
    }

    // NOTE: tk holds sum(e_k*inv); w_k applied below at partial write
    #pragma unroll
    for (int k = 0; k < K_; k++) { float v = warpSum(tk[k]); if (t == 0) tks[w][k] = v; }
    __syncthreads();   // also guards buf reuse
    #pragma unroll
    for (int c = 0; c < 4; c++) {
        buf[w * 128 + t + 32 * c]        = zc[c];
        buf[1024 + w * 128 + t + 32 * c] = lc[c];
        buf[2048 + w * 128 + t + 32 * c] = ab[c];
    }
    __syncthreads();
    if (tid < 128) {
        float s = 0.0f, s2 = 0.0f, s3 = 0.0f;
        #pragma unroll
        for (int ww = 0; ww < 8; ww++) {
            s  += buf[ww * 128 + tid];
            s2 += buf[1024 + ww * 128 + tid];
            s3 += buf[2048 + ww * 128 + tid];
        }
        Zcolp_g[(size_t)(b * NB1_ + blk) * F_ + tid]   = s;
        ligcolp_g[(size_t)(b * NB1_ + blk) * F_ + tid] = s2;
        abarp_g[(size_t)(b * NB1_ + blk) * F_ + tid]   = s3;
    } else if (tid < 128 + K_) {
        int k = tid - 128;
        float s = 0.0f;
        #pragma unroll
        for (int ww = 0; ww < 8; ww++) s += tks[ww][k];
        tstrp_g[(size_t)(b * NB1_ + blk) * 8 + k] = s * wshr[k];
    }
}

// ============ K3: lean E pass — craw + unscaled Pw/Cw partials =============
__global__ void __launch_bounds__(256, 6) k3_epass(const float* __restrict__ protein_emb,
                        const float* __restrict__ ligand_emb,
                        const float* __restrict__ fg_mask,
                        const float* __restrict__ prot_mask,
                        const float* __restrict__ Wr, const float* __restrict__ Wf,
                        const float* __restrict__ W1, const float* __restrict__ W2) {
    int b = blockIdx.y, blk = blockIdx.x;
    int tid = threadIdx.x, w = tid >> 5, t = tid & 31;
    int f = tid & 127, q = tid >> 7;

    __shared__ float lco_sm[128];
    __shared__ float zsm[2][128], lsm[2][128];
    __shared__ float stage[2048];

    // L2 prefetch of head weights + ligand (covers all lines across 512 blocks)
    {
        int gb = b * NB3_ + blk;                       // 0..511
        long gid = (long)gb * 256 + tid;               // 0..131071
        const long n1 = 4208;                          // W1 lines
        const long n2 = 4096;                          // W2 lines
        const long nr = 512;                           // Wr/Wf lines each
        const long nl = 8192;                          // ligand lines (1MB)
        if (gid < n1)                      l2pf((const char*)W1 + gid * 128);
        else if (gid < n1+n2)              l2pf((const char*)W2 + (gid-n1) * 128);
        else if (gid < n1+n2+nr)           l2pf((const char*)Wr + (gid-n1-n2) * 128);
        else if (gid < n1+n2+2*nr)         l2pf((const char*)Wf + (gid-n1-n2-nr) * 128);
        else if (gid < n1+n2+2*nr+nl)      l2pf((const char*)ligand_emb + (gid-n1-n2-2*nr) * 128);
    }

    // lcoef from k1 column partials
    float zs = 0.0f, ls = 0.0f;
    for (int s = q * 16; s < q * 16 + 16; s++) {
        zs += Zcolp_g[(size_t)(b * NB1_ + s) * F_ + f];
        ls += ligcolp_g[(size_t)(b * NB1_ + s) * F_ + f];
    }
    zsm[q][f] = zs; lsm[q][f] = ls;
    __syncthreads();
    if (tid < 128) {
        float Zc  = zsm[0][tid] + zsm[1][tid];
        float lgc = lsm[0][tid] + lsm[1][tid];
        lco_sm[tid] = __fdividef(lgc * fg_mask[b * F_ + tid], Zc);
    }
    __syncthreads();
    float lcoc[4];
    #pragma unroll
    for (int c = 0; c < 4; c++) lcoc[c] = lco_sm[t + 32 * c];

    // row loop: 8 warps x 4 rows
    float Pa[4] = {0,0,0,0}, Ca[4] = {0,0,0,0};
    int rbase = blk * 32 + w * 4;
    #pragma unroll
    for (int i = 0; i < 4; i++) {
        int r = rbase + i;
        float ps = pscore_g[b * R_ + r];
        float pm = prot_mask[b * R_ + r];
        float mexr = __expf(-(1.0f - pm) * 1e9f);
        float E[4], dv = 0.0f;
        #pragma unroll
        for (int c = 0; c < 4; c++) {
            E[c] = E_g[(size_t)(b * R_ + r) * F_ + t + 32 * c];
            dv += lcoc[c] * E[c];
        }
        float craw = mexr * warpAllSum(dv);
        #pragma unroll
        for (int c = 0; c < 4; c++) {
            float Pv = protein_emb[(size_t)(b * R_ + r) * D_ + t + 32 * c];
            Pa[c] += ps * Pv;
            Ca[c] += craw * Pv;
        }
    }

    __syncthreads();
    #pragma unroll
    for (int c = 0; c < 4; c++) {
        stage[w * 128 + t + 32 * c]        = Pa[c];
        stage[1024 + w * 128 + t + 32 * c] = Ca[c];
    }
    __syncthreads();
    if (tid < 128) {
        float s = 0.0f;
        #pragma unroll
        for (int ww = 0; ww < 8; ww++) s += stage[ww * 128 + tid];
        Pwp_g[(size_t)(b * NB3_ + blk) * D_ + tid] = s;
    } else {
        float s = 0.0f;
        #pragma unroll
        for (int ww = 0; ww < 8; ww++) s += stage[1024 + ww * 128 + f];
        Cwp_g[(size_t)(b * NB3_ + blk) * D_ + f] = s;
    }
}

// ============ KHEAD: pools + feat + norm + MLP (one block per batch) =======
__global__ void __launch_bounds__(512, 2) khead(const float* __restrict__ ligand_emb,
                        const float* __restrict__ fg_mask,
                        const float* __restrict__ Wr, const float* __restrict__ br,
                        const float* __restrict__ Wf, const float* __restrict__ bf,
                        const float* __restrict__ W1, const float* __restrict__ b1,
                        const float* __restrict__ W2, const float* __restrict__ b2,
                        const float* __restrict__ W3, const float* __restrict__ b3,
                        float* __restrict__ dout, int osz) {
    int b = blockIdx.x, tid = threadIdx.x, w = tid >> 5, t = tid & 31;
    int f = tid & 127, q = tid >> 7;

    __shared__ float red[32];
    __shared__ float big[2048];
    __shared__ float lw_sm[128], la_s[128];
    __shared__ float Pws[128], Cws[128];
    __shared__ float gs[128], Ls[128];
    __shared__ float feat[FEAT_ + 1];
    __shared__ float h1[H_], h2[H2_];
    __shared__ float tst[8];

    if (b == 0) for (int i = B_ + B_ * FEAT_ + tid; i < osz; i += 512) dout[i] = 0.0f;

    // psum
    float v = pscore_g[b * R_ + tid] + pscore_g[b * R_ + 512 + tid];
    float psum = blockReduceSum(v, red);
    float ip = __fdividef(1.0f, psum + 1e-8f);
    float spw = psum * ip;

    // ligcol sums -> lsum, lw
    {
        float ls = 0.0f;
        for (int s = q * 8; s < q * 8 + 8; s++) ls += ligcolp_g[(size_t)(b * NB1_ + s) * F_ + f];
        big[q * 128 + f] = ls;
    }
    __syncthreads();
    float lw0 = 0.0f;
    if (tid < 128) {
        float lgc = big[tid] + big[128+tid] + big[256+tid] + big[384+tid];
        lw0 = lgc * fg_mask[b * F_ + tid];
    }
    float lsum = blockReduceSum(lw0, red);
    float il = __fdividef(1.0f, lsum + 1e-8f);
    float slw = lsum * il;
    if (tid < 128) lw_sm[tid] = lw0 * il;

    // slot sums: abar (NB1 slots), Pw/Cw (NB3 slots)
    {
        float aA = 0.0f, aP = 0.0f, aC = 0.0f;
        #pragma unroll
        for (int s = 0; s < 8; s++) {
            int s1 = q * 8 + s;
            aA += abarp_g[(size_t)(b * NB1_ + s1) * F_ + f];
            aP += Pwp_g[(size_t)(b * NB3_ + s1) * D_ + f];
            aC += Cwp_g[(size_t)(b * NB3_ + s1) * D_ + f];
        }
        big[512 + q * 128 + f]  = aA;
        big[1024 + q * 128 + f] = aP;
        big[1536 + q * 128 + f] = aC;
    }
    __syncthreads();
    if (tid < 128) {
        float aA = big[512+tid] + big[640+tid] + big[768+tid] + big[896+tid];
        float aP = big[1024+tid] + big[1152+tid] + big[1280+tid] + big[1408+tid];
        float aC = big[1536+tid] + big[1664+tid] + big[1792+tid] + big[1920+tid];
        float fg = fg_mask[b * F_ + tid];
        float mexf = __expf(-(1.0f - fg) * 1e9f);
        la_s[tid] = aA * mexf * ip;
        Pws[tid] = aP * ip;
        Cws[tid] = aC * il;
    }
    if (tid < K_) {
        float s = 0.0f;
        #pragma unroll
        for (int s2 = 0; s2 < NB1_; s2++) s += tstrp_g[(size_t)(b * NB1_ + s2) * 8 + tid];
        tst[tid] = s;
    }
    __syncthreads();

    // ligand pooling: 4 f-chunks x 128 d
    float ag = 0.0f, aL = 0.0f;
    #pragma unroll 8
    for (int i = 0; i < 32; i++) {
        int ff = q * 32 + i;
        float lv = ligand_emb[(size_t)(b * F_ + ff) * D_ + f];
        ag += la_s[ff] * lv;
        aL += lw_sm[ff] * lv;
    }
    big[q * 128 + f] = ag;
    big[512 + q * 128 + f] = aL;
    __syncthreads();
    if (tid < 128) {
        gs[tid] = big[tid] + big[128+tid] + big[256+tid] + big[384+tid];
        Ls[tid] = big[512+tid] + big[640+tid] + big[768+tid] + big[896+tid];
    }
    __syncthreads();

    // feat rows: warps 0-7 -> Wr/gs, 8-15 -> Wf/Cws; 4 rows per iteration
    {
        const float* Wm = (w < 8) ? Wr : Wf;
        const float* vec = (w < 8) ? gs : Cws;
        int rb = (w & 7) * 16;
        #pragma unroll 1
        for (int i = 0; i < 4; i++) {
            int r0 = rb + i * 4;
            float p0=0.f,p1=0.f,p2=0.f,p3=0.f;
            #pragma unroll
            for (int u = 0; u < 4; u++) {
                int j = t + 32 * u;
                float g = vec[j];
                p0 += Wm[(r0+0)*D_ + j] * g;
                p1 += Wm[(r0+1)*D_ + j] * g;
                p2 += Wm[(r0+2)*D_ + j] * g;
                p3 += Wm[(r0+3)*D_ + j] * g;
            }
            p0 = warpSum(p0); p1 = warpSum(p1); p2 = warpSum(p2); p3 = warpSum(p3);
            if (t == 0) {
                if (w < 8) {
                    feat[r0+0] = Pws[r0+0] + p0 + spw * br[r0+0];
                    feat[r0+1] = Pws[r0+1] + p1 + spw * br[r0+1];
                    feat[r0+2] = Pws[r0+2] + p2 + spw * br[r0+2];
                    feat[r0+3] = Pws[r0+3] + p3 + spw * br[r0+3];
                } else {
                    feat[128+r0+0] = Ls[r0+0] + p0 + slw * bf[r0+0];
                    feat[128+r0+1] = Ls[r0+1] + p1 + slw * bf[r0+1];
                    feat[128+r0+2] = Ls[r0+2] + p2 + slw * bf[r0+2];
                    feat[128+r0+3] = Ls[r0+3] + p3 + slw * bf[r0+3];
                }
            }
        }
    }
    if (tid < K_) feat[2 * D_ + tid] = tst[tid];
    __syncthreads();

    // norm + normalized-feat output
    float sv = (tid < FEAT_) ? feat[tid] * feat[tid] : 0.0f;
    float nrm = blockReduceSum(sv, red);
    float inv = 1.0f / fmaxf(sqrtf(nrm), 1e-12f);
    if (tid < FEAT_) {
        int oi = B_ + b * FEAT_ + tid;
        if (oi < osz) dout[oi] = feat[tid] * inv;
    }

    // MLP layer 1: 512 rows, 32/warp, 4 per iteration
    {
        int rb = w * 32;
        #pragma unroll 1
        for (int i = 0; i < 8; i++) {
            int r0 = rb + i * 4;
            float p0=0.f,p1=0.f,p2=0.f,p3=0.f;
            #pragma unroll
            for (int u = 0; u < 8; u++) {
                int j = t + 32 * u;
                float fv = feat[j];
                p0 += W1[(r0+0)*FEAT_ + j] * fv;
                p1 += W1[(r0+1)*FEAT_ + j] * fv;
                p2 += W1[(r0+2)*FEAT_ + j] * fv;
                p3 += W1[(r0+3)*FEAT_ + j] * fv;
            }
            if (t < 7) {
                int j = 256 + t;
                float fv = feat[j];
                p0 += W1[(r0+0)*FEAT_ + j] * fv;
                p1 += W1[(r0+1)*FEAT_ + j] * fv;
                p2 += W1[(r0+2)*FEAT_ + j] * fv;
                p3 += W1[(r0+3)*FEAT_ + j] * fv;
            }
            p0 = warpSum(p0); p1 = warpSum(p1); p2 = warpSum(p2); p3 = warpSum(p3);
            if (t == 0) {
                h1[r0+0] = fmaxf(p0 + b1[r0+0], 0.0f);
                h1[r0+1] = fmaxf(p1 + b1[r0+1], 0.0f);
                h1[r0+2] = fmaxf(p2 + b1[r0+2], 0.0f);
                h1[r0+3] = fmaxf(p3 + b1[r0+3], 0.0f);
            }
        }
    }
    __syncthreads();

    // MLP layer 2: 256 rows, 16/warp, 2 per iteration
    {
        int rb = w * 16;
        #pragma unroll 1
        for (int i = 0; i < 8; i++) {
            int r0 = rb + i * 2;
            float p0=0.f,p1=0.f;
            #pragma unroll
            for (int u = 0; u < 16; u++) {
                int j = t + 32 * u;
                float hv = h1[j];
                p0 += W2[(r0+0)*H_ + j] * hv;
                p1 += W2[(r0+1)*H_ + j] * hv;
            }
            p0 = warpSum(p0); p1 = warpSum(p1);
            if (t == 0) {
                h2[r0+0] = fmaxf(p0 + b2[r0+0], 0.0f);
                h2[r0+1] = fmaxf(p1 + b2[r0+1], 0.0f);
            }
        }
    }
    __syncthreads();
    float pv = (tid < H2_) ? W3[tid] * h2[tid] : 0.0f;
    float pred = blockReduceSum(pv, red);
    if (tid == 0 && b < osz) dout[b] = pred + b3[0];
}

// ---------------- launch ----------------
extern "C" void kernel_launch(void* const* d_in, const int* in_sizes, int n_in,
                              void* d_out, int out_size) {
    const float* lig    = (const float*)d_in[0];
    const float* prot   = (const float*)d_in[1];
    const float* logits = (const float*)d_in[2];
    const float* fg     = (const float*)d_in[3];
    const float* pmsk   = (const float*)d_in[4];
    const float* tw     = (const float*)d_in[5];
    const float* Wr = (const float*)d_in[6];  const float* br = (const float*)d_in[7];
    const float* Wf = (const float*)d_in[8];  const float* bf = (const float*)d_in[9];
    const float* W1 = (const float*)d_in[10]; const float* b1 = (const float*)d_in[11];
    const float* W2 = (const float*)d_in[12]; const float* b2 = (const float*)d_in[13];
    const float* W3 = (const float*)d_in[14]; const float* b3 = (const float*)d_in[15];
    float* out = (float*)d_out;

    k1_logits<<<dim3(NB1_, B_), 256>>>(logits, fg, pmsk, tw);
    k3_epass<<<dim3(NB3_, B_), 256>>>(prot, lig, fg, pmsk, Wr, Wf, W1, W2);
    khead<<<B_, 512>>>(lig, fg, Wr, br, Wf, bf, W1, b1, W2, b2, W3, b3, out, out_size);
}

// round 10
// speedup vs baseline: 1.0499x; 1.0499x over previous
#include <cuda_runtime.h>
#include <cuda_fp16.h>
#include <cstdint>
#include <math.h>

#define B_ 16
#define R_ 1024
#define F_ 128
#define D_ 128
#define K_ 7
#define H_ 512
#define H2_ 256
#define FEAT_ 263   // 2*D + K
#define NB1_ 32     // k1 blocks per batch (32 rows each)
#define NB3_ 32     // k3 blocks per batch (32 rows each)

// ---------------- device scratch (static, allocation-free) ----------------
__device__ __half E_h[B_ * R_ * F_];         // exp(masked S), fp16 (E in [1,3.74])
__device__ float Zrow_g[B_ * R_];            // sum_f E*mexf
__device__ float pscore_g[B_ * R_];          // S.sum(f) * pm
__device__ float Zcolp_g[B_ * NB1_ * F_];    // partial: sum_r E*mexr
__device__ float ligcolp_g[B_ * NB1_ * F_];  // partial: sum_r S
__device__ float abarp_g[B_ * NB1_ * F_];    // partial: sum_r coef_r*E
__device__ float tstrp_g[B_ * NB1_ * 8];     // partial type strength
__device__ float Pwp_g[B_ * NB3_ * D_];      // partial: sum_r pscore_r*P  (unscaled)
__device__ float Cwp_g[B_ * NB3_ * D_];      // partial: sum_r craw_r*P    (unscaled)

// ---------------- helpers ----------------
__device__ __forceinline__ float warpSum(float v) {
    #pragma unroll
    for (int o = 16; o > 0; o >>= 1) v += __shfl_down_sync(0xffffffffu, v, o);
    return v;
}
__device__ __forceinline__ float warpAllSum(float v) {
    #pragma unroll
    for (int o = 16; o > 0; o >>= 1) v += __shfl_xor_sync(0xffffffffu, v, o);
    return v;
}
__device__ __forceinline__ float blockReduceSum(float v, float* sm) {
    int lane = threadIdx.x & 31, w = threadIdx.x >> 5;
    int nw = (blockDim.x + 31) >> 5;
    v = warpSum(v);
    if (lane == 0) sm[w] = v;
    __syncthreads();
    float r = (threadIdx.x < nw) ? sm[threadIdx.x] : 0.0f;
    if (w == 0) r = warpSum(r);
    if (threadIdx.x == 0) sm[0] = r;
    __syncthreads();
    r = sm[0];
    __syncthreads();
    return r;
}
__device__ __forceinline__ void l2pf(const void* p) {
    asm volatile("prefetch.global.L2 [%0];" :: "l"(p));
}

// ============ K1: logits pass — lean softmax, fp16 E store =================
__global__ void __launch_bounds__(256, 4) k1_logits(const float* __restrict__ logits,
                          const float* __restrict__ fg_mask,
                          const float* __restrict__ prot_mask,
                          const float* __restrict__ tw) {
    int b = blockIdx.y, blk = blockIdx.x;
    int tid = threadIdx.x, w = tid >> 5, t = tid & 31;

    __shared__ float buf[8 * 896];     // 28KB: 8 logits rows / staging
    __shared__ float tks[8][8];
    __shared__ float wsh_s[8];

    if (tid < K_) {
        float x = tw[tid];
        wsh_s[tid] = fmaxf(x, 0.0f) + log1pf(expf(-fabsf(x)));
    }
    __syncthreads();
    float wshr[K_];
    #pragma unroll
    for (int k = 0; k < K_; k++) wshr[k] = wsh_s[k];

    float fgc[4], mexfc[4];
    #pragma unroll
    for (int c = 0; c < 4; c++) {
        fgc[c] = fg_mask[b * F_ + t + 32 * c];
        mexfc[c] = __expf(-(1.0f - fgc[c]) * 1e9f);
    }

    float zc[4] = {0,0,0,0}, lc[4] = {0,0,0,0}, ab[4] = {0,0,0,0};
    float tk[K_];
    #pragma unroll
    for (int k = 0; k < K_; k++) tk[k] = 0.0f;

    int r0 = blk * 32;
    for (int tile = 0; tile < 4; tile++) {
        const float4* src = (const float4*)(logits + (size_t)(b * R_ + r0 + tile * 8) * 896);
        __syncthreads();
        #pragma unroll
        for (int i = 0; i < 7; i++) ((float4*)buf)[tid + 256 * i] = src[tid + 256 * i];
        __syncthreads();

        int r = r0 + tile * 8 + w;
        float pm = prot_mask[b * R_ + r];
        float mexr = __expf(-(1.0f - pm) * 1e9f);
        float pmf[4];
        #pragma unroll
        for (int c = 0; c < 4; c++) pmf[c] = pm * fgc[c];
        float rowS = 0.0f, rowE = 0.0f;
        float Ev[4];

        #pragma unroll
        for (int c = 0; c < 4; c++) {
            int fb = w * 896 + (t + 32 * c) * 7;     // lane stride 7: conflict-free
            float e0 = __expf(buf[fb+0]);
            float e1 = __expf(buf[fb+1]);
            float e2 = __expf(buf[fb+2]);
            float e3 = __expf(buf[fb+3]);
            float e4 = __expf(buf[fb+4]);
            float e5 = __expf(buf[fb+5]);
            float e6 = __expf(buf[fb+6]);
            float s = ((e0+e1)+(e2+e3)) + ((e4+e5)+e6);
            float inv = __fdividef(1.0f, s);
            float h = e0*wshr[0];
            h = fmaf(e1, wshr[1], h);
            h = fmaf(e2, wshr[2], h);
            h = fmaf(e3, wshr[3], h);
            h = fmaf(e4, wshr[4], h);
            h = fmaf(e5, wshr[5], h);
            h = fmaf(e6, wshr[6], h);
            tk[0] = fmaf(e0, inv, tk[0]);
            tk[1] = fmaf(e1, inv, tk[1]);
            tk[2] = fmaf(e2, inv, tk[2]);
            tk[3] = fmaf(e3, inv, tk[3]);
            tk[4] = fmaf(e4, inv, tk[4]);
            tk[5] = fmaf(e5, inv, tk[5]);
            tk[6] = fmaf(e6, inv, tk[6]);
            float Sm = h * inv * pmf[c];
            float E = __expf(Sm);
            E_h[(size_t)(b * R_ + r) * F_ + t + 32 * c] = __float2half_rn(E);
            Ev[c] = E;
            rowS += Sm;
            rowE = fmaf(E, mexfc[c], rowE);
            zc[c] = fmaf(E, mexr, zc[c]);
            lc[c] += Sm;
        }
        rowS = warpAllSum(rowS);
        rowE = warpAllSum(rowE);
        float ps = rowS * pm;
        if (t == 0) { pscore_g[b * R_ + r] = ps; Zrow_g[b * R_ + r] = rowE; }
        float coef = __fdividef(ps, rowE);
        #pragma unroll
        for (int c = 0; c < 4; c++) ab[c] = fmaf(coef, Ev[c], ab[c]);
    }

    #pragma unroll
    for (int k = 0; k < K_; k++) { float v = warpSum(tk[k]); if (t == 0) tks[w][k] = v; }
    __syncthreads();   // also guards buf reuse
    #pragma unroll
    for (int c = 0; c < 4; c++) {
        buf[w * 128 + t + 32 * c]        = zc[c];
        buf[1024 + w * 128 + t + 32 * c] = lc[c];
        buf[2048 + w * 128 + t + 32 * c] = ab[c];
    }
    __syncthreads();
    if (tid < 128) {
        float s = 0.0f, s2 = 0.0f, s3 = 0.0f;
        #pragma unroll
        for (int ww = 0; ww < 8; ww++) {
            s  += buf[ww * 128 + tid];
            s2 += buf[1024 + ww * 128 + tid];
            s3 += buf[2048 + ww * 128 + tid];
        }
        Zcolp_g[(size_t)(b * NB1_ + blk) * F_ + tid]   = s;
        ligcolp_g[(size_t)(b * NB1_ + blk) * F_ + tid] = s2;
        abarp_g[(size_t)(b * NB1_ + blk) * F_ + tid]   = s3;
    } else if (tid < 128 + K_) {
        int k = tid - 128;
        float s = 0.0f;
        #pragma unroll
        for (int ww = 0; ww < 8; ww++) s += tks[ww][k];
        tstrp_g[(size_t)(b * NB1_ + blk) * 8 + k] = s * wshr[k];
    }
#if __CUDA_ARCH__ >= 900
    cudaTriggerProgrammaticLaunchCompletion();
#endif
}

// ============ K3: lean E pass — craw + unscaled Pw/Cw partials =============
__global__ void __launch_bounds__(256, 6) k3_epass(const float* __restrict__ protein_emb,
                        const float* __restrict__ ligand_emb,
                        const float* __restrict__ fg_mask,
                        const float* __restrict__ prot_mask,
                        const float* __restrict__ Wr, const float* __restrict__ Wf,
                        const float* __restrict__ W1, const float* __restrict__ W2) {
    int b = blockIdx.y, blk = blockIdx.x;
    int tid = threadIdx.x, w = tid >> 5, t = tid & 31;
    int f = tid & 127, q = tid >> 7;

    __shared__ float lco_sm[128];
    __shared__ float zsm[2][128], lsm[2][128];
    __shared__ float stage[2048];

    // PDL prolog: L2 prefetch of head weights + ligand (independent of k1)
    {
        int gb = b * NB3_ + blk;                       // 0..511
        long gid = (long)gb * 256 + tid;               // 0..131071
        const long n1 = 4208;                          // W1 lines
        const long n2 = 4096;                          // W2 lines
        const long nr = 512;                           // Wr/Wf lines each
        const long nl = 8192;                          // ligand lines (1MB)
        if (gid < n1)                      l2pf((const char*)W1 + gid * 128);
        else if (gid < n1+n2)              l2pf((const char*)W2 + (gid-n1) * 128);
        else if (gid < n1+n2+nr)           l2pf((const char*)Wr + (gid-n1-n2) * 128);
        else if (gid < n1+n2+2*nr)         l2pf((const char*)Wf + (gid-n1-n2-nr) * 128);
        else if (gid < n1+n2+2*nr+nl)      l2pf((const char*)ligand_emb + (gid-n1-n2-2*nr) * 128);
    }
#if __CUDA_ARCH__ >= 900
    cudaGridDependencySynchronize();
#endif

    // lcoef from k1 column partials
    float zs = 0.0f, ls = 0.0f;
    for (int s = q * 16; s < q * 16 + 16; s++) {
        zs += Zcolp_g[(size_t)(b * NB1_ + s) * F_ + f];
        ls += ligcolp_g[(size_t)(b * NB1_ + s) * F_ + f];
    }
    zsm[q][f] = zs; lsm[q][f] = ls;
    __syncthreads();
    if (tid < 128) {
        float Zc  = zsm[0][tid] + zsm[1][tid];
        float lgc = lsm[0][tid] + lsm[1][tid];
        lco_sm[tid] = __fdividef(lgc * fg_mask[b * F_ + tid], Zc);
    }
    __syncthreads();
    float lcoc[4];
    #pragma unroll
    for (int c = 0; c < 4; c++) lcoc[c] = lco_sm[t + 32 * c];

    // row loop: 8 warps x 4 rows
    float Pa[4] = {0,0,0,0}, Ca[4] = {0,0,0,0};
    int rbase = blk * 32 + w * 4;
    #pragma unroll
    for (int i = 0; i < 4; i++) {
        int r = rbase + i;
        float ps = pscore_g[b * R_ + r];
        float pm = prot_mask[b * R_ + r];
        float mexr = __expf(-(1.0f - pm) * 1e9f);
        float E[4], dv = 0.0f;
        #pragma unroll
        for (int c = 0; c < 4; c++) {
            E[c] = __half2float(E_h[(size_t)(b * R_ + r) * F_ + t + 32 * c]);
            dv += lcoc[c] * E[c];
        }
        float craw = mexr * warpAllSum(dv);
        #pragma unroll
        for (int c = 0; c < 4; c++) {
            float Pv = protein_emb[(size_t)(b * R_ + r) * D_ + t + 32 * c];
            Pa[c] += ps * Pv;
            Ca[c] += craw * Pv;
        }
    }

    __syncthreads();
    #pragma unroll
    for (int c = 0; c < 4; c++) {
        stage[w * 128 + t + 32 * c]        = Pa[c];
        stage[1024 + w * 128 + t + 32 * c] = Ca[c];
    }
    __syncthreads();
    if (tid < 128) {
        float s = 0.0f;
        #pragma unroll
        for (int ww = 0; ww < 8; ww++) s += stage[ww * 128 + tid];
        Pwp_g[(size_t)(b * NB3_ + blk) * D_ + tid] = s;
    } else {
        float s = 0.0f;
        #pragma unroll
        for (int ww = 0; ww < 8; ww++) s += stage[1024 + ww * 128 + f];
        Cwp_g[(size_t)(b * NB3_ + blk) * D_ + f] = s;
    }
#if __CUDA_ARCH__ >= 900
    cudaTriggerProgrammaticLaunchCompletion();
#endif
}

// ============ KHEAD: pools + feat + norm + MLP (one block per batch) =======
__global__ void __launch_bounds__(512, 2) khead(const float* __restrict__ ligand_emb,
                        const float* __restrict__ fg_mask,
                        const float* __restrict__ Wr, const float* __restrict__ br,
                        const float* __restrict__ Wf, const float* __restrict__ bf,
                        const float* __restrict__ W1, const float* __restrict__ b1,
                        const float* __restrict__ W2, const float* __restrict__ b2,
                        const float* __restrict__ W3, const float* __restrict__ b3,
                        float* __restrict__ dout, int osz) {
    int b = blockIdx.x, tid = threadIdx.x, w = tid >> 5, t = tid & 31;
    int f = tid & 127, q = tid >> 7;

    __shared__ float red[32];
    __shared__ float big[2048];
    __shared__ float lw_sm[128], la_s[128];
    __shared__ float Pws[128], Cws[128];
    __shared__ float gs[128], Ls[128];
    __shared__ float feat[FEAT_ + 1];
    __shared__ float h1[H_], h2[H2_];
    __shared__ float tst[8];

    // PDL prolog: tail-zero of dout (written only by this kernel)
    if (b == 0) for (int i = B_ + B_ * FEAT_ + tid; i < osz; i += 512) dout[i] = 0.0f;
#if __CUDA_ARCH__ >= 900
    cudaGridDependencySynchronize();
#endif

    // psum
    float v = pscore_g[b * R_ + tid] + pscore_g[b * R_ + 512 + tid];
    float psum = blockReduceSum(v, red);
    float ip = __fdividef(1.0f, psum + 1e-8f);
    float spw = psum * ip;

    // ligcol sums -> lsum, lw
    {
        float ls = 0.0f;
        for (int s = q * 8; s < q * 8 + 8; s++) ls += ligcolp_g[(size_t)(b * NB1_ + s) * F_ + f];
        big[q * 128 + f] = ls;
    }
    __syncthreads();
    float lw0 = 0.0f;
    if (tid < 128) {
        float lgc = big[tid] + big[128+tid] + big[256+tid] + big[384+tid];
        lw0 = lgc * fg_mask[b * F_ + tid];
    }
    float lsum = blockReduceSum(lw0, red);
    float il = __fdividef(1.0f, lsum + 1e-8f);
    float slw = lsum * il;
    if (tid < 128) lw_sm[tid] = lw0 * il;

    // slot sums: abar (NB1 slots), Pw/Cw (NB3 slots)
    {
        float aA = 0.0f, aP = 0.0f, aC = 0.0f;
        #pragma unroll
        for (int s = 0; s < 8; s++) {
            int s1 = q * 8 + s;
            aA += abarp_g[(size_t)(b * NB1_ + s1) * F_ + f];
            aP += Pwp_g[(size_t)(b * NB3_ + s1) * D_ + f];
            aC += Cwp_g[(size_t)(b * NB3_ + s1) * D_ + f];
        }
        big[512 + q * 128 + f]  = aA;
        big[1024 + q * 128 + f] = aP;
        big[1536 + q * 128 + f] = aC;
    }
    __syncthreads();
    if (tid < 128) {
        float aA = big[512+tid] + big[640+tid] + big[768+tid] + big[896+tid];
        float aP = big[1024+tid] + big[1152+tid] + big[1280+tid] + big[1408+tid];
        float aC = big[1536+tid] + big[1664+tid] + big[1792+tid] + big[1920+tid];
        float fg = fg_mask[b * F_ + tid];
        float mexf = __expf(-(1.0f - fg) * 1e9f);
        la_s[tid] = aA * mexf * ip;
        Pws[tid] = aP * ip;
        Cws[tid] = aC * il;
    }
    if (tid < K_) {
        float s = 0.0f;
        #pragma unroll
        for (int s2 = 0; s2 < NB1_; s2++) s += tstrp_g[(size_t)(b * NB1_ + s2) * 8 + tid];
        tst[tid] = s;
    }
    __syncthreads();

    // ligand pooling: 4 f-chunks x 128 d
    float ag = 0.0f, aL = 0.0f;
    #pragma unroll 8
    for (int i = 0; i < 32; i++) {
        int ff = q * 32 + i;
        float lv = ligand_emb[(size_t)(b * F_ + ff) * D_ + f];
        ag += la_s[ff] * lv;
        aL += lw_sm[ff] * lv;
    }
    big[q * 128 + f] = ag;
    big[512 + q * 128 + f] = aL;
    __syncthreads();
    if (tid < 128) {
        gs[tid] = big[tid] + big[128+tid] + big[256+tid] + big[384+tid];
        Ls[tid] = big[512+tid] + big[640+tid] + big[768+tid] + big[896+tid];
    }
    __syncthreads();

    // feat rows: warps 0-7 -> Wr/gs, 8-15 -> Wf/Cws; 4 rows per iteration
    {
        const float* Wm = (w < 8) ? Wr : Wf;
        const float* vec = (w < 8) ? gs : Cws;
        int rb = (w & 7) * 16;
        #pragma unroll 1
        for (int i = 0; i < 4; i++) {
            int r0 = rb + i * 4;
            float p0=0.f,p1=0.f,p2=0.f,p3=0.f;
            #pragma unroll
            for (int u = 0; u < 4; u++) {
                int j = t + 32 * u;
                float g = vec[j];
                p0 += Wm[(r0+0)*D_ + j] * g;
                p1 += Wm[(r0+1)*D_ + j] * g;
                p2 += Wm[(r0+2)*D_ + j] * g;
                p3 += Wm[(r0+3)*D_ + j] * g;
            }
            p0 = warpSum(p0); p1 = warpSum(p1); p2 = warpSum(p2); p3 = warpSum(p3);
            if (t == 0) {
                if (w < 8) {
                    feat[r0+0] = Pws[r0+0] + p0 + spw * br[r0+0];
                    feat[r0+1] = Pws[r0+1] + p1 + spw * br[r0+1];
                    feat[r0+2] = Pws[r0+2] + p2 + spw * br[r0+2];
                    feat[r0+3] = Pws[r0+3] + p3 + spw * br[r0+3];
                } else {
                    feat[128+r0+0] = Ls[r0+0] + p0 + slw * bf[r0+0];
                    feat[128+r0+1] = Ls[r0+1] + p1 + slw * bf[r0+1];
                    feat[128+r0+2] = Ls[r0+2] + p2 + slw * bf[r0+2];
                    feat[128+r0+3] = Ls[r0+3] + p3 + slw * bf[r0+3];
                }
            }
        }
    }
    if (tid < K_) feat[2 * D_ + tid] = tst[tid];
    __syncthreads();

    // norm + normalized-feat output
    float sv = (tid < FEAT_) ? feat[tid] * feat[tid] : 0.0f;
    float nrm = blockReduceSum(sv, red);
    float inv = 1.0f / fmaxf(sqrtf(nrm), 1e-12f);
    if (tid < FEAT_) {
        int oi = B_ + b * FEAT_ + tid;
        if (oi < osz) dout[oi] = feat[tid] * inv;
    }

    // MLP layer 1: 512 rows, 32/warp, 4 per iteration
    {
        int rb = w * 32;
        #pragma unroll 1
        for (int i = 0; i < 8; i++) {
            int r0 = rb + i * 4;
            float p0=0.f,p1=0.f,p2=0.f,p3=0.f;
            #pragma unroll
            for (int u = 0; u < 8; u++) {
                int j = t + 32 * u;
                float fv = feat[j];
                p0 += W1[(r0+0)*FEAT_ + j] * fv;
                p1 += W1[(r0+1)*FEAT_ + j] * fv;
                p2 += W1[(r0+2)*FEAT_ + j] * fv;
                p3 += W1[(r0+3)*FEAT_ + j] * fv;
            }
            if (t < 7) {
                int j = 256 + t;
                float fv = feat[j];
                p0 += W1[(r0+0)*FEAT_ + j] * fv;
                p1 += W1[(r0+1)*FEAT_ + j] * fv;
                p2 += W1[(r0+2)*FEAT_ + j] * fv;
                p3 += W1[(r0+3)*FEAT_ + j] * fv;
            }
            p0 = warpSum(p0); p1 = warpSum(p1); p2 = warpSum(p2); p3 = warpSum(p3);
            if (t == 0) {
                h1[r0+0] = fmaxf(p0 + b1[r0+0], 0.0f);
                h1[r0+1] = fmaxf(p1 + b1[r0+1], 0.0f);
                h1[r0+2] = fmaxf(p2 + b1[r0+2], 0.0f);
                h1[r0+3] = fmaxf(p3 + b1[r0+3], 0.0f);
            }
        }
    }
    __syncthreads();

    // MLP layer 2: 256 rows, 16/warp, 2 per iteration
    {
        int rb = w * 16;
        #pragma unroll 1
        for (int i = 0; i < 8; i++) {
            int r0 = rb + i * 2;
            float p0=0.f,p1=0.f;
            #pragma unroll
            for (int u = 0; u < 16; u++) {
                int j = t + 32 * u;
                float hv = h1[j];
                p0 += W2[(r0+0)*H_ + j] * hv;
                p1 += W2[(r0+1)*H_ + j] * hv;
            }
            p0 = warpSum(p0); p1 = warpSum(p1);
            if (t == 0) {
                h2[r0+0] = fmaxf(p0 + b2[r0+0], 0.0f);
                h2[r0+1] = fmaxf(p1 + b2[r0+1], 0.0f);
            }
        }
    }
    __syncthreads();
    float pv = (tid < H2_) ? W3[tid] * h2[tid] : 0.0f;
    float pred = blockReduceSum(pv, red);
    if (tid == 0 && b < osz) dout[b] = pred + b3[0];
}

// ---------------- launch ----------------
extern "C" void kernel_launch(void* const* d_in, const int* in_sizes, int n_in,
                              void* d_out, int out_size) {
    const float* lig    = (const float*)d_in[0];
    const float* prot   = (const float*)d_in[1];
    const float* logits = (const float*)d_in[2];
    const float* fg     = (const float*)d_in[3];
    const float* pmsk   = (const float*)d_in[4];
    const float* tw     = (const float*)d_in[5];
    const float* Wr = (const float*)d_in[6];  const float* br = (const float*)d_in[7];
    const float* Wf = (const float*)d_in[8];  const float* bf = (const float*)d_in[9];
    const float* W1 = (const float*)d_in[10]; const float* b1 = (const float*)d_in[11];
    const float* W2 = (const float*)d_in[12]; const float* b2 = (const float*)d_in[13];
    const float* W3 = (const float*)d_in[14]; const float* b3 = (const float*)d_in[15];
    float* out = (float*)d_out;

    k1_logits<<<dim3(NB1_, B_), 256>>>(logits, fg, pmsk, tw);

    // k3 with PDL: overlaps its prefetch prolog with k1's tail
    {
        cudaLaunchConfig_t cfg = {};
        cfg.gridDim = dim3(NB3_, B_);
        cfg.blockDim = dim3(256, 1, 1);
        cfg.dynamicSmemBytes = 0;
        cfg.stream = 0;
        cudaLaunchAttribute attrs[1];
        attrs[0].id = cudaLaunchAttributeProgrammaticStreamSerialization;
        attrs[0].val.programmaticStreamSerializationAllowed = 1;
        cfg.attrs = attrs;
        cfg.numAttrs = 1;
        cudaLaunchKernelEx(&cfg, k3_epass, prot, lig, fg, pmsk, Wr, Wf, W1, W2);
    }

    // khead with PDL: overlaps dout tail-zero + launch latency with k3's tail
    {
        cudaLaunchConfig_t cfg = {};
        cfg.gridDim = dim3(B_, 1, 1);
        cfg.blockDim = dim3(512, 1, 1);
        cfg.dynamicSmemBytes = 0;
        cfg.stream = 0;
        cudaLaunchAttribute attrs[1];
        attrs[0].id = cudaLaunchAttributeProgrammaticStreamSerialization;
        attrs[0].val.programmaticStreamSerializationAllowed = 1;
        cfg.attrs = attrs;
        cfg.numAttrs = 1;
        cudaLaunchKernelEx(&cfg, khead, lig, fg, Wr, br, Wf, bf,
                           W1, b1, W2, b2, W3, b3, out, out_size);
    }
}

// round 11
// speedup vs baseline: 1.0688x; 1.0180x over previous
#include <cuda_runtime.h>
#include <cuda_fp16.h>
#include <cstdint>
#include <math.h>

#define B_ 16
#define R_ 1024
#define F_ 128
#define D_ 128
#define K_ 7
#define H_ 512
#define H2_ 256
#define FEAT_ 263   // 2*D + K
#define NB1_ 32     // k1 blocks per batch (32 rows each)
#define NB3_ 32     // k3 blocks per batch (32 rows each)

// ---------------- device scratch (static, allocation-free) ----------------
__device__ __half E_h[B_ * R_ * F_];         // exp(masked S), fp16 (E in [1,3.74])
__device__ float Zrow_g[B_ * R_];            // sum_f E*mexf
__device__ float pscore_g[B_ * R_];          // S.sum(f) * pm
__device__ float Zcolp_g[B_ * NB1_ * F_];    // partial: sum_r E*mexr
__device__ float ligcolp_g[B_ * NB1_ * F_];  // partial: sum_r S
__device__ float abarp_g[B_ * NB1_ * F_];    // partial: sum_r coef_r*E
__device__ float tstrp_g[B_ * NB1_ * 8];     // partial type strength
__device__ float Pwp_g[B_ * NB3_ * D_];      // partial: sum_r pscore_r*P  (unscaled)
__device__ float Cwp_g[B_ * NB3_ * D_];      // partial: sum_r craw_r*P    (unscaled)

// ---------------- helpers ----------------
__device__ __forceinline__ float warpSum(float v) {
    #pragma unroll
    for (int o = 16; o > 0; o >>= 1) v += __shfl_down_sync(0xffffffffu, v, o);
    return v;
}
__device__ __forceinline__ float warpAllSum(float v) {
    #pragma unroll
    for (int o = 16; o > 0; o >>= 1) v += __shfl_xor_sync(0xffffffffu, v, o);
    return v;
}
__device__ __forceinline__ float blockReduceSum(float v, float* sm) {
    int lane = threadIdx.x & 31, w = threadIdx.x >> 5;
    int nw = (blockDim.x + 31) >> 5;
    v = warpSum(v);
    if (lane == 0) sm[w] = v;
    __syncthreads();
    float r = (threadIdx.x < nw) ? sm[threadIdx.x] : 0.0f;
    if (w == 0) r = warpSum(r);
    if (threadIdx.x == 0) sm[0] = r;
    __syncthreads();
    r = sm[0];
    __syncthreads();
    return r;
}
__device__ __forceinline__ void l2pf(const void* p) {
    asm volatile("prefetch.global.L2 [%0];" :: "l"(p));
}

// ============ K1: logits pass — BARRIER-FREE warp-private staging ==========
__global__ void __launch_bounds__(256, 4) k1_logits(const float* __restrict__ logits,
                          const float* __restrict__ fg_mask,
                          const float* __restrict__ prot_mask,
                          const float* __restrict__ tw) {
    int b = blockIdx.y, blk = blockIdx.x;
    int tid = threadIdx.x, w = tid >> 5, t = tid & 31;

    __shared__ float buf[8][896];      // 28KB: one row slice per warp
    __shared__ float tks[8][8];
    __shared__ float wsh_s[8];

    if (tid < K_) {
        float x = tw[tid];
        wsh_s[tid] = fmaxf(x, 0.0f) + log1pf(expf(-fabsf(x)));
    }
    __syncthreads();
    float wshr[K_];
    #pragma unroll
    for (int k = 0; k < K_; k++) wshr[k] = wsh_s[k];

    float fgc[4], mexfc[4];
    #pragma unroll
    for (int c = 0; c < 4; c++) {
        fgc[c] = fg_mask[b * F_ + t + 32 * c];
        mexfc[c] = __expf(-(1.0f - fgc[c]) * 1e9f);
    }

    float zc[4] = {0,0,0,0}, lc[4] = {0,0,0,0}, ab[4] = {0,0,0,0};
    float tk[K_];
    #pragma unroll
    for (int k = 0; k < K_; k++) tk[k] = 0.0f;

    int r0 = blk * 32 + w * 4;         // this warp's 4 rows
    float4* dst = (float4*)buf[w];

    for (int i = 0; i < 4; i++) {
        int r = r0 + i;
        // warp-private staging: 7 coalesced float4 loads, no block sync
        const float4* src = (const float4*)(logits + (size_t)(b * R_ + r) * 896);
        #pragma unroll
        for (int j = 0; j < 7; j++) dst[t + 32 * j] = src[t + 32 * j];
        __syncwarp();

        float pm = prot_mask[b * R_ + r];
        float mexr = __expf(-(1.0f - pm) * 1e9f);
        float pmf[4];
        #pragma unroll
        for (int c = 0; c < 4; c++) pmf[c] = pm * fgc[c];
        float rowS = 0.0f, rowE = 0.0f;
        float Ev[4];

        #pragma unroll
        for (int c = 0; c < 4; c++) {
            const float* bp = buf[w] + (t + 32 * c) * 7;   // stride-7: conflict-free
            float e0 = __expf(bp[0]);
            float e1 = __expf(bp[1]);
            float e2 = __expf(bp[2]);
            float e3 = __expf(bp[3]);
            float e4 = __expf(bp[4]);
            float e5 = __expf(bp[5]);
            float e6 = __expf(bp[6]);
            float s = ((e0+e1)+(e2+e3)) + ((e4+e5)+e6);
            float inv = __fdividef(1.0f, s);
            float h = e0*wshr[0];
            h = fmaf(e1, wshr[1], h);
            h = fmaf(e2, wshr[2], h);
            h = fmaf(e3, wshr[3], h);
            h = fmaf(e4, wshr[4], h);
            h = fmaf(e5, wshr[5], h);
            h = fmaf(e6, wshr[6], h);
            tk[0] = fmaf(e0, inv, tk[0]);
            tk[1] = fmaf(e1, inv, tk[1]);
            tk[2] = fmaf(e2, inv, tk[2]);
            tk[3] = fmaf(e3, inv, tk[3]);
            tk[4] = fmaf(e4, inv, tk[4]);
            tk[5] = fmaf(e5, inv, tk[5]);
            tk[6] = fmaf(e6, inv, tk[6]);
            float Sm = h * inv * pmf[c];
            float E = __expf(Sm);
            E_h[(size_t)(b * R_ + r) * F_ + t + 32 * c] = __float2half_rn(E);
            Ev[c] = E;
            rowS += Sm;
            rowE = fmaf(E, mexfc[c], rowE);
            zc[c] = fmaf(E, mexr, zc[c]);
            lc[c] += Sm;
        }
        rowS = warpAllSum(rowS);
        rowE = warpAllSum(rowE);
        float ps = rowS * pm;
        if (t == 0) { pscore_g[b * R_ + r] = ps; Zrow_g[b * R_ + r] = rowE; }
        float coef = __fdividef(ps, rowE);
        #pragma unroll
        for (int c = 0; c < 4; c++) ab[c] = fmaf(coef, Ev[c], ab[c]);
        __syncwarp();   // all LDS reads of buf[w] done before next row overwrites
    }

    // epilogue: single block-wide reduction into deterministic partial slots
    #pragma unroll
    for (int k = 0; k < K_; k++) { float v = warpSum(tk[k]); if (t == 0) tks[w][k] = v; }
    __syncthreads();
    float* bb = &buf[0][0];
    #pragma unroll
    for (int c = 0; c < 4; c++) {
        bb[w * 128 + t + 32 * c]        = zc[c];
        bb[1024 + w * 128 + t + 32 * c] = lc[c];
        bb[2048 + w * 128 + t + 32 * c] = ab[c];
    }
    __syncthreads();
    if (tid < 128) {
        float s = 0.0f, s2 = 0.0f, s3 = 0.0f;
        #pragma unroll
        for (int ww = 0; ww < 8; ww++) {
            s  += bb[ww * 128 + tid];
            s2 += bb[1024 + ww * 128 + tid];
            s3 += bb[2048 + ww * 128 + tid];
        }
        Zcolp_g[(size_t)(b * NB1_ + blk) * F_ + tid]   = s;
        ligcolp_g[(size_t)(b * NB1_ + blk) * F_ + tid] = s2;
        abarp_g[(size_t)(b * NB1_ + blk) * F_ + tid]   = s3;
    } else if (tid < 128 + K_) {
        int k = tid - 128;
        float s = 0.0f;
        #pragma unroll
        for (int ww = 0; ww < 8; ww++) s += tks[ww][k];
        tstrp_g[(size_t)(b * NB1_ + blk) * 8 + k] = s * wshr[k];
    }
#if __CUDA_ARCH__ >= 900
    cudaTriggerProgrammaticLaunchCompletion();
#endif
}

// ============ K3: lean E pass — craw + unscaled Pw/Cw partials =============
__global__ void __launch_bounds__(256, 6) k3_epass(const float* __restrict__ protein_emb,
                        const float* __restrict__ ligand_emb,
                        const float* __restrict__ fg_mask,
                        const float* __restrict__ prot_mask,
                        const float* __restrict__ Wr, const float* __restrict__ Wf,
                        const float* __restrict__ W1, const float* __restrict__ W2) {
    int b = blockIdx.y, blk = blockIdx.x;
    int tid = threadIdx.x, w = tid >> 5, t = tid & 31;
    int f = tid & 127, q = tid >> 7;

    __shared__ float lco_sm[128];
    __shared__ float zsm[2][128], lsm[2][128];
    __shared__ float stage[2048];

    // PDL prolog: L2 prefetch of head weights + ligand (independent of k1)
    {
        int gb = b * NB3_ + blk;                       // 0..511
        long gid = (long)gb * 256 + tid;               // 0..131071
        const long n1 = 4208;                          // W1 lines
        const long n2 = 4096;                          // W2 lines
        const long nr = 512;                           // Wr/Wf lines each
        const long nl = 8192;                          // ligand lines (1MB)
        if (gid < n1)                      l2pf((const char*)W1 + gid * 128);
        else if (gid < n1+n2)              l2pf((const char*)W2 + (gid-n1) * 128);
        else if (gid < n1+n2+nr)           l2pf((const char*)Wr + (gid-n1-n2) * 128);
        else if (gid < n1+n2+2*nr)         l2pf((const char*)Wf + (gid-n1-n2-nr) * 128);
        else if (gid < n1+n2+2*nr+nl)      l2pf((const char*)ligand_emb + (gid-n1-n2-2*nr) * 128);
    }
#if __CUDA_ARCH__ >= 900
    cudaGridDependencySynchronize();
#endif

    // lcoef from k1 column partials
    float zs = 0.0f, ls = 0.0f;
    for (int s = q * 16; s < q * 16 + 16; s++) {
        zs += Zcolp_g[(size_t)(b * NB1_ + s) * F_ + f];
        ls += ligcolp_g[(size_t)(b * NB1_ + s) * F_ + f];
    }
    zsm[q][f] = zs; lsm[q][f] = ls;
    __syncthreads();
    if (tid < 128) {
        float Zc  = zsm[0][tid] + zsm[1][tid];
        float lgc = lsm[0][tid] + lsm[1][tid];
        lco_sm[tid] = __fdividef(lgc * fg_mask[b * F_ + tid], Zc);
    }
    __syncthreads();
    float lcoc[4];
    #pragma unroll
    for (int c = 0; c < 4; c++) lcoc[c] = lco_sm[t + 32 * c];

    // row loop: 8 warps x 4 rows
    float Pa[4] = {0,0,0,0}, Ca[4] = {0,0,0,0};
    int rbase = blk * 32 + w * 4;
    #pragma unroll
    for (int i = 0; i < 4; i++) {
        int r = rbase + i;
        float ps = pscore_g[b * R_ + r];
        float pm = prot_mask[b * R_ + r];
        float mexr = __expf(-(1.0f - pm) * 1e9f);
        float E[4], dv = 0.0f;
        #pragma unroll
        for (int c = 0; c < 4; c++) {
            E[c] = __half2float(E_h[(size_t)(b * R_ + r) * F_ + t + 32 * c]);
            dv += lcoc[c] * E[c];
        }
        float craw = mexr * warpAllSum(dv);
        #pragma unroll
        for (int c = 0; c < 4; c++) {
            float Pv = protein_emb[(size_t)(b * R_ + r) * D_ + t + 32 * c];
            Pa[c] += ps * Pv;
            Ca[c] += craw * Pv;
        }
    }

    __syncthreads();
    #pragma unroll
    for (int c = 0; c < 4; c++) {
        stage[w * 128 + t + 32 * c]        = Pa[c];
        stage[1024 + w * 128 + t + 32 * c] = Ca[c];
    }
    __syncthreads();
    if (tid < 128) {
        float s = 0.0f;
        #pragma unroll
        for (int ww = 0; ww < 8; ww++) s += stage[ww * 128 + tid];
        Pwp_g[(size_t)(b * NB3_ + blk) * D_ + tid] = s;
    } else {
        float s = 0.0f;
        #pragma unroll
        for (int ww = 0; ww < 8; ww++) s += stage[1024 + ww * 128 + f];
        Cwp_g[(size_t)(b * NB3_ + blk) * D_ + f] = s;
    }
#if __CUDA_ARCH__ >= 900
    cudaTriggerProgrammaticLaunchCompletion();
#endif
}

// ============ KHEAD: 1024 threads — pools + feat + norm + MLP ==============
__global__ void __launch_bounds__(1024, 1) khead(const float* __restrict__ ligand_emb,
                        const float* __restrict__ fg_mask,
                        const float* __restrict__ Wr, const float* __restrict__ br,
                        const float* __restrict__ Wf, const float* __restrict__ bf,
                        const float* __restrict__ W1, const float* __restrict__ b1,
                        const float* __restrict__ W2, const float* __restrict__ b2,
                        const float* __restrict__ W3, const float* __restrict__ b3,
                        float* __restrict__ dout, int osz) {
    int b = blockIdx.x, tid = threadIdx.x, w = tid >> 5, t = tid & 31;
    int f = tid & 127, q = tid >> 7;     // q in 0..7

    __shared__ float red[32];
    __shared__ float big[3072];
    __shared__ float lw_sm[128], la_s[128];
    __shared__ float Pws[128], Cws[128];
    __shared__ float gs[128], Ls[128];
    __shared__ float feat[FEAT_ + 1];
    __shared__ float h1[H_], h2[H2_];
    __shared__ float tst[8];

    // PDL prolog
    if (b == 0) for (int i = B_ + B_ * FEAT_ + tid; i < osz; i += 1024) dout[i] = 0.0f;
#if __CUDA_ARCH__ >= 900
    cudaGridDependencySynchronize();
#endif

    // psum: exactly one pscore element per thread
    float v = pscore_g[b * R_ + tid];
    float psum = blockReduceSum(v, red);
    float ip = __fdividef(1.0f, psum + 1e-8f);
    float spw = psum * ip;

    // ligcol sums (32 slots; 8 groups of 4)
    {
        float ls = 0.0f;
        #pragma unroll
        for (int s = 0; s < 4; s++) ls += ligcolp_g[(size_t)(b * NB1_ + q * 4 + s) * F_ + f];
        big[q * 128 + f] = ls;
    }
    __syncthreads();
    float lw0 = 0.0f;
    if (tid < 128) {
        float lgc = 0.0f;
        #pragma unroll
        for (int j = 0; j < 8; j++) lgc += big[j * 128 + tid];
        lw0 = lgc * fg_mask[b * F_ + tid];
    }
    float lsum = blockReduceSum(lw0, red);
    float il = __fdividef(1.0f, lsum + 1e-8f);
    float slw = lsum * il;
    if (tid < 128) lw_sm[tid] = lw0 * il;

    // slot sums: abar/Pw/Cw (32 slots; 8 groups of 4)
    {
        float aA = 0.0f, aP = 0.0f, aC = 0.0f;
        #pragma unroll
        for (int s = 0; s < 4; s++) {
            int s1 = q * 4 + s;
            aA += abarp_g[(size_t)(b * NB1_ + s1) * F_ + f];
            aP += Pwp_g[(size_t)(b * NB3_ + s1) * D_ + f];
            aC += Cwp_g[(size_t)(b * NB3_ + s1) * D_ + f];
        }
        big[q * 128 + f]        = aA;
        big[1024 + q * 128 + f] = aP;
        big[2048 + q * 128 + f] = aC;
    }
    __syncthreads();
    if (tid < 128) {
        float aA = 0.0f, aP = 0.0f, aC = 0.0f;
        #pragma unroll
        for (int j = 0; j < 8; j++) {
            aA += big[j * 128 + tid];
            aP += big[1024 + j * 128 + tid];
            aC += big[2048 + j * 128 + tid];
        }
        float fg = fg_mask[b * F_ + tid];
        float mexf = __expf(-(1.0f - fg) * 1e9f);
        la_s[tid] = aA * mexf * ip;
        Pws[tid] = aP * ip;
        Cws[tid] = aC * il;
    }
    if (tid < K_) {
        float s = 0.0f;
        #pragma unroll
        for (int s2 = 0; s2 < NB1_; s2++) s += tstrp_g[(size_t)(b * NB1_ + s2) * 8 + tid];
        tst[tid] = s;
    }
    __syncthreads();

    // ligand pooling: 8 f-chunks x 128 d
    {
        float ag = 0.0f, aL = 0.0f;
        #pragma unroll
        for (int i = 0; i < 16; i++) {
            int ff = q * 16 + i;
            float lv = ligand_emb[(size_t)(b * F_ + ff) * D_ + f];
            ag += la_s[ff] * lv;
            aL += lw_sm[ff] * lv;
        }
        big[q * 128 + f] = ag;
        big[1024 + q * 128 + f] = aL;
    }
    __syncthreads();
    if (tid < 128) {
        float g = 0.0f, L = 0.0f;
        #pragma unroll
        for (int j = 0; j < 8; j++) { g += big[j * 128 + tid]; L += big[1024 + j * 128 + tid]; }
        gs[tid] = g; Ls[tid] = L;
    }
    __syncthreads();

    // feat rows: warps 0-15 -> Wr/gs, 16-31 -> Wf/Cws; 8 rows/warp, 4 per iter
    {
        const float* Wm = (w < 16) ? Wr : Wf;
        const float* vec = (w < 16) ? gs : Cws;
        int rb = (w & 15) * 8;
        #pragma unroll 1
        for (int i = 0; i < 2; i++) {
            int r0 = rb + i * 4;
            float p0=0.f,p1=0.f,p2=0.f,p3=0.f;
            #pragma unroll
            for (int u = 0; u < 4; u++) {
                int j = t + 32 * u;
                float g = vec[j];
                p0 += Wm[(r0+0)*D_ + j] * g;
                p1 += Wm[(r0+1)*D_ + j] * g;
                p2 += Wm[(r0+2)*D_ + j] * g;
                p3 += Wm[(r0+3)*D_ + j] * g;
            }
            p0 = warpSum(p0); p1 = warpSum(p1); p2 = warpSum(p2); p3 = warpSum(p3);
            if (t == 0) {
                if (w < 16) {
                    feat[r0+0] = Pws[r0+0] + p0 + spw * br[r0+0];
                    feat[r0+1] = Pws[r0+1] + p1 + spw * br[r0+1];
                    feat[r0+2] = Pws[r0+2] + p2 + spw * br[r0+2];
                    feat[r0+3] = Pws[r0+3] + p3 + spw * br[r0+3];
                } else {
                    feat[128+r0+0] = Ls[r0+0] + p0 + slw * bf[r0+0];
                    feat[128+r0+1] = Ls[r0+1] + p1 + slw * bf[r0+1];
                    feat[128+r0+2] = Ls[r0+2] + p2 + slw * bf[r0+2];
                    feat[128+r0+3] = Ls[r0+3] + p3 + slw * bf[r0+3];
                }
            }
        }
    }
    if (tid < K_) feat[2 * D_ + tid] = tst[tid];
    __syncthreads();

    // norm + normalized-feat output
    float sv = (tid < FEAT_) ? feat[tid] * feat[tid] : 0.0f;
    float nrm = blockReduceSum(sv, red);
    float inv = 1.0f / fmaxf(sqrtf(nrm), 1e-12f);
    if (tid < FEAT_) {
        int oi = B_ + b * FEAT_ + tid;
        if (oi < osz) dout[oi] = feat[tid] * inv;
    }

    // MLP layer 1: 512 rows, 16/warp, 4 per iteration
    {
        int rb = w * 16;
        #pragma unroll 1
        for (int i = 0; i < 4; i++) {
            int r0 = rb + i * 4;
            float p0=0.f,p1=0.f,p2=0.f,p3=0.f;
            #pragma unroll
            for (int u = 0; u < 8; u++) {
                int j = t + 32 * u;
                float fv = feat[j];
                p0 += W1[(r0+0)*FEAT_ + j] * fv;
                p1 += W1[(r0+1)*FEAT_ + j] * fv;
                p2 += W1[(r0+2)*FEAT_ + j] * fv;
                p3 += W1[(r0+3)*FEAT_ + j] * fv;
            }
            if (t < 7) {
                int j = 256 + t;
                float fv = feat[j];
                p0 += W1[(r0+0)*FEAT_ + j] * fv;
                p1 += W1[(r0+1)*FEAT_ + j] * fv;
                p2 += W1[(r0+2)*FEAT_ + j] * fv;
                p3 += W1[(r0+3)*FEAT_ + j] * fv;
            }
            p0 = warpSum(p0); p1 = warpSum(p1); p2 = warpSum(p2); p3 = warpSum(p3);
            if (t == 0) {
                h1[r0+0] = fmaxf(p0 + b1[r0+0], 0.0f);
                h1[r0+1] = fmaxf(p1 + b1[r0+1], 0.0f);
                h1[r0+2] = fmaxf(p2 + b1[r0+2], 0.0f);
                h1[r0+3] = fmaxf(p3 + b1[r0+3], 0.0f);
            }
        }
    }
    __syncthreads();

    // MLP layer 2: 256 rows, 8/warp, 2 per iteration
    {
        int rb = w * 8;
        #pragma unroll 1
        for (int i = 0; i < 4; i++) {
            int r0 = rb + i * 2;
            float p0=0.f,p1=0.f;
            #pragma unroll
            for (int u = 0; u < 16; u++) {
                int j = t + 32 * u;
                float hv = h1[j];
                p0 += W2[(r0+0)*H_ + j] * hv;
                p1 += W2[(r0+1)*H_ + j] * hv;
            }
            p0 = warpSum(p0); p1 = warpSum(p1);
            if (t == 0) {
                h2[r0+0] = fmaxf(p0 + b2[r0+0], 0.0f);
                h2[r0+1] = fmaxf(p1 + b2[r0+1], 0.0f);
            }
        }
    }
    __syncthreads();
    float pv = (tid < H2_) ? W3[tid] * h2[tid] : 0.0f;
    float pred = blockReduceSum(pv, red);
    if (tid == 0 && b < osz) dout[b] = pred + b3[0];
}

// ---------------- launch ----------------
extern "C" void kernel_launch(void* const* d_in, const int* in_sizes, int n_in,
                              void* d_out, int out_size) {
    const float* lig    = (const float*)d_in[0];
    const float* prot   = (const float*)d_in[1];
    const float* logits = (const float*)d_in[2];
    const float* fg     = (const float*)d_in[3];
    const float* pmsk   = (const float*)d_in[4];
    const float* tw     = (const float*)d_in[5];
    const float* Wr = (const float*)d_in[6];  const float* br = (const float*)d_in[7];
    const float* Wf = (const float*)d_in[8];  const float* bf = (const float*)d_in[9];
    const float* W1 = (const float*)d_in[10]; const float* b1 = (const float*)d_in[11];
    const float* W2 = (const float*)d_in[12]; const float* b2 = (const float*)d_in[13];
    const float* W3 = (const float*)d_in[14]; const float* b3 = (const float*)d_in[15];
    float* out = (float*)d_out;

    k1_logits<<<dim3(NB1_, B_), 256>>>(logits, fg, pmsk, tw);

    // k3 with PDL: overlaps its prefetch prolog with k1's tail
    {
        cudaLaunchConfig_t cfg = {};
        cfg.gridDim = dim3(NB3_, B_);
        cfg.blockDim = dim3(256, 1, 1);
        cfg.dynamicSmemBytes = 0;
        cfg.stream = 0;
        cudaLaunchAttribute attrs[1];
        attrs[0].id = cudaLaunchAttributeProgrammaticStreamSerialization;
        attrs[0].val.programmaticStreamSerializationAllowed = 1;
        cfg.attrs = attrs;
        cfg.numAttrs = 1;
        cudaLaunchKernelEx(&cfg, k3_epass, prot, lig, fg, pmsk, Wr, Wf, W1, W2);
    }

    // khead with PDL: overlaps dout tail-zero + launch latency with k3's tail
    {
        cudaLaunchConfig_t cfg = {};
        cfg.gridDim = dim3(B_, 1, 1);
        cfg.blockDim = dim3(1024, 1, 1);
        cfg.dynamicSmemBytes = 0;
        cfg.stream = 0;
        cudaLaunchAttribute attrs[1];
        attrs[0].id = cudaLaunchAttributeProgrammaticStreamSerialization;
        attrs[0].val.programmaticStreamSerializationAllowed = 1;
        cfg.attrs = attrs;
        cfg.numAttrs = 1;
        cudaLaunchKernelEx(&cfg, khead, lig, fg, Wr, br, Wf, bf,
                           W1, b1, W2, b2, W3, b3, out, out_size);
    }
}

// round 12
// speedup vs baseline: 1.1204x; 1.0483x over previous
#include <cuda_runtime.h>
#include <cuda_fp16.h>
#include <cstdint>
#include <math.h>

#define B_ 16
#define R_ 1024
#define F_ 128
#define D_ 128
#define K_ 7
#define H_ 512
#define H2_ 256
#define FEAT_ 263   // 2*D + K
#define NB1_ 32     // k1 blocks per batch (32 rows each)
#define NB3_ 32     // k3 blocks per batch (32 rows each)

// ---------------- device scratch (static, allocation-free) ----------------
__device__ __half E_h[B_ * R_ * F_];         // exp(masked S), fp16 (E in [1,3.74])
__device__ float Zrow_g[B_ * R_];            // sum_f E*mexf
__device__ float pscore_g[B_ * R_];          // S.sum(f) * pm
__device__ float Zcolp_g[B_ * NB1_ * F_];    // partial: sum_r E*mexr
__device__ float ligcolp_g[B_ * NB1_ * F_];  // partial: sum_r S
__device__ float abarp_g[B_ * NB1_ * F_];    // partial: sum_r coef_r*E
__device__ float tstrp_g[B_ * NB1_ * 8];     // partial type strength
__device__ float Pwp_g[B_ * NB3_ * D_];      // partial: sum_r pscore_r*P  (unscaled)
__device__ float Cwp_g[B_ * NB3_ * D_];      // partial: sum_r craw_r*P    (unscaled)

// ---------------- helpers ----------------
__device__ __forceinline__ float warpSum(float v) {
    #pragma unroll
    for (int o = 16; o > 0; o >>= 1) v += __shfl_down_sync(0xffffffffu, v, o);
    return v;
}
__device__ __forceinline__ float warpAllSum(float v) {
    #pragma unroll
    for (int o = 16; o > 0; o >>= 1) v += __shfl_xor_sync(0xffffffffu, v, o);
    return v;
}
__device__ __forceinline__ float blockReduceSum(float v, float* sm) {
    int lane = threadIdx.x & 31, w = threadIdx.x >> 5;
    int nw = (blockDim.x + 31) >> 5;
    v = warpSum(v);
    if (lane == 0) sm[w] = v;
    __syncthreads();
    float r = (threadIdx.x < nw) ? sm[threadIdx.x] : 0.0f;
    if (w == 0) r = warpSum(r);
    if (threadIdx.x == 0) sm[0] = r;
    __syncthreads();
    r = sm[0];
    __syncthreads();
    return r;
}
__device__ __forceinline__ void l2pf(const void* p) {
    asm volatile("prefetch.global.L2 [%0];" :: "l"(p));
}

// per-element softmax+weights macro (uses wshr, tk, rowS, rowE, mexr in scope)
#define ELEM(X0,X1,X2,X3,X4,X5,X6, PMF, MEXF, EOUT, ZC, LC) do {              \
    float e0_=__expf(X0), e1_=__expf(X1), e2_=__expf(X2), e3_=__expf(X3);      \
    float e4_=__expf(X4), e5_=__expf(X5), e6_=__expf(X6);                      \
    float s_ = ((e0_+e1_)+(e2_+e3_))+((e4_+e5_)+e6_);                          \
    float inv_ = __fdividef(1.0f, s_);                                         \
    float h_ = e0_*wshr[0]; h_=fmaf(e1_,wshr[1],h_); h_=fmaf(e2_,wshr[2],h_);  \
    h_=fmaf(e3_,wshr[3],h_); h_=fmaf(e4_,wshr[4],h_);                          \
    h_=fmaf(e5_,wshr[5],h_); h_=fmaf(e6_,wshr[6],h_);                          \
    tk[0]=fmaf(e0_,inv_,tk[0]); tk[1]=fmaf(e1_,inv_,tk[1]);                    \
    tk[2]=fmaf(e2_,inv_,tk[2]); tk[3]=fmaf(e3_,inv_,tk[3]);                    \
    tk[4]=fmaf(e4_,inv_,tk[4]); tk[5]=fmaf(e5_,inv_,tk[5]);                    \
    tk[6]=fmaf(e6_,inv_,tk[6]);                                                \
    float Sm_ = h_*inv_*(PMF);                                                 \
    float E_ = __expf(Sm_);                                                    \
    EOUT = E_; rowS += Sm_; rowE = fmaf(E_, (MEXF), rowE);                     \
    ZC = fmaf(E_, mexr, ZC); LC += Sm_;                                        \
} while(0)

// ============ K1: logits pass — f=4t+j lane mapping, vectorized LSU ========
__global__ void __launch_bounds__(256, 4) k1_logits(const float* __restrict__ logits,
                          const float* __restrict__ fg_mask,
                          const float* __restrict__ prot_mask,
                          const float* __restrict__ tw) {
    int b = blockIdx.y, blk = blockIdx.x;
    int tid = threadIdx.x, w = tid >> 5, t = tid & 31;

    __shared__ __align__(16) float buf[8][896];   // 28KB: one row per warp
    __shared__ float tks[8][8];
    __shared__ float wsh_s[8];

    if (tid < K_) {
        float x = tw[tid];
        wsh_s[tid] = fmaxf(x, 0.0f) + log1pf(expf(-fabsf(x)));
    }
    __syncthreads();
    float wshr[K_];
    #pragma unroll
    for (int k = 0; k < K_; k++) wshr[k] = wsh_s[k];

    float4 fg4 = ((const float4*)(fg_mask + b * F_))[t];
    float mexf0 = __expf(-(1.0f - fg4.x) * 1e9f);
    float mexf1 = __expf(-(1.0f - fg4.y) * 1e9f);
    float mexf2 = __expf(-(1.0f - fg4.z) * 1e9f);
    float mexf3 = __expf(-(1.0f - fg4.w) * 1e9f);

    float zc0=0.f,zc1=0.f,zc2=0.f,zc3=0.f;
    float lc0=0.f,lc1=0.f,lc2=0.f,lc3=0.f;
    float ab0=0.f,ab1=0.f,ab2=0.f,ab3=0.f;
    float tk[K_];
    #pragma unroll
    for (int k = 0; k < K_; k++) tk[k] = 0.0f;

    int r0 = blk * 32 + w * 4;
    float4* dst = (float4*)buf[w];
    const float4* bp4 = (const float4*)(buf[w] + t * 28);   // 112t bytes, 16-aligned

    for (int i = 0; i < 4; i++) {
        int r = r0 + i;
        const float4* src = (const float4*)(logits + (size_t)(b * R_ + r) * 896);
        #pragma unroll
        for (int j = 0; j < 7; j++) dst[t + 32 * j] = src[t + 32 * j];
        __syncwarp();

        float pm = prot_mask[b * R_ + r];
        float mexr = __expf(-(1.0f - pm) * 1e9f);
        float rowS = 0.0f, rowE = 0.0f;
        float E0, E1, E2, E3;

        // elements j=0,1 from floats 0..15 (LDS.128, quarter-warp conflict-free)
        {
            float4 v0 = bp4[0], v1 = bp4[1], v2 = bp4[2], v3 = bp4[3];
            ELEM(v0.x, v0.y, v0.z, v0.w, v1.x, v1.y, v1.z, pm * fg4.x, mexf0, E0, zc0, lc0);
            ELEM(v1.w, v2.x, v2.y, v2.z, v2.w, v3.x, v3.y, pm * fg4.y, mexf1, E1, zc1, lc1);
            float4 v4 = bp4[4], v5 = bp4[5], v6 = bp4[6];
            ELEM(v3.z, v3.w, v4.x, v4.y, v4.z, v4.w, v5.x, pm * fg4.z, mexf2, E2, zc2, lc2);
            ELEM(v5.y, v5.z, v5.w, v6.x, v6.y, v6.z, v6.w, pm * fg4.w, mexf3, E3, zc3, lc3);
        }

        // packed fp16 store: 4 halfs = one STG.64
        {
            __half2 ha = __halves2half2(__float2half_rn(E0), __float2half_rn(E1));
            __half2 hb = __halves2half2(__float2half_rn(E2), __float2half_rn(E3));
            uint2 pk;
            pk.x = *reinterpret_cast<unsigned int*>(&ha);
            pk.y = *reinterpret_cast<unsigned int*>(&hb);
            ((uint2*)(E_h + (size_t)(b * R_ + r) * F_))[t] = pk;
        }

        rowS = warpAllSum(rowS);
        rowE = warpAllSum(rowE);
        float ps = rowS * pm;
        if (t == 0) { pscore_g[b * R_ + r] = ps; Zrow_g[b * R_ + r] = rowE; }
        float coef = __fdividef(ps, rowE);
        ab0 = fmaf(coef, E0, ab0);
        ab1 = fmaf(coef, E1, ab1);
        ab2 = fmaf(coef, E2, ab2);
        ab3 = fmaf(coef, E3, ab3);
        __syncwarp();
    }

    // epilogue: block-wide reduction into deterministic partial slots
    #pragma unroll
    for (int k = 0; k < K_; k++) { float v = warpSum(tk[k]); if (t == 0) tks[w][k] = v; }
    __syncthreads();
    float* bb = &buf[0][0];
    float4* bb4 = (float4*)bb;
    bb4[w * 32 + t]       = make_float4(zc0, zc1, zc2, zc3);
    bb4[256 + w * 32 + t] = make_float4(lc0, lc1, lc2, lc3);
    bb4[512 + w * 32 + t] = make_float4(ab0, ab1, ab2, ab3);
    __syncthreads();
    if (tid < 128) {
        float s = 0.0f, s2 = 0.0f, s3 = 0.0f;
        #pragma unroll
        for (int ww = 0; ww < 8; ww++) {
            s  += bb[ww * 128 + tid];
            s2 += bb[1024 + ww * 128 + tid];
            s3 += bb[2048 + ww * 128 + tid];
        }
        Zcolp_g[(size_t)(b * NB1_ + blk) * F_ + tid]   = s;
        ligcolp_g[(size_t)(b * NB1_ + blk) * F_ + tid] = s2;
        abarp_g[(size_t)(b * NB1_ + blk) * F_ + tid]   = s3;
    } else if (tid < 128 + K_) {
        int k = tid - 128;
        float s = 0.0f;
        #pragma unroll
        for (int ww = 0; ww < 8; ww++) s += tks[ww][k];
        tstrp_g[(size_t)(b * NB1_ + blk) * 8 + k] = s * wshr[k];
    }
#if __CUDA_ARCH__ >= 900
    cudaTriggerProgrammaticLaunchCompletion();
#endif
}

// ============ K3: vectorized E pass — craw + unscaled Pw/Cw partials =======
__global__ void __launch_bounds__(256, 6) k3_epass(const float* __restrict__ protein_emb,
                        const float* __restrict__ ligand_emb,
                        const float* __restrict__ fg_mask,
                        const float* __restrict__ prot_mask,
                        const float* __restrict__ Wr, const float* __restrict__ Wf,
                        const float* __restrict__ W1, const float* __restrict__ W2) {
    int b = blockIdx.y, blk = blockIdx.x;
    int tid = threadIdx.x, w = tid >> 5, t = tid & 31;
    int f = tid & 127, q = tid >> 7;

    __shared__ __align__(16) float lco_sm[128];
    __shared__ float zsm[2][128], lsm[2][128];
    __shared__ __align__(16) float stage[2048];

    // PDL prolog: L2 prefetch of head weights + ligand (independent of k1)
    {
        int gb = b * NB3_ + blk;                       // 0..511
        long gid = (long)gb * 256 + tid;               // 0..131071
        const long n1 = 4208;                          // W1 lines
        const long n2 = 4096;                          // W2 lines
        const long nr = 512;                           // Wr/Wf lines each
        const long nl = 8192;                          // ligand lines (1MB)
        if (gid < n1)                      l2pf((const char*)W1 + gid * 128);
        else if (gid < n1+n2)              l2pf((const char*)W2 + (gid-n1) * 128);
        else if (gid < n1+n2+nr)           l2pf((const char*)Wr + (gid-n1-n2) * 128);
        else if (gid < n1+n2+2*nr)         l2pf((const char*)Wf + (gid-n1-n2-nr) * 128);
        else if (gid < n1+n2+2*nr+nl)      l2pf((const char*)ligand_emb + (gid-n1-n2-2*nr) * 128);
    }
#if __CUDA_ARCH__ >= 900
    cudaGridDependencySynchronize();
#endif

    // lcoef from k1 column partials
    float zs = 0.0f, ls = 0.0f;
    for (int s = q * 16; s < q * 16 + 16; s++) {
        zs += Zcolp_g[(size_t)(b * NB1_ + s) * F_ + f];
        ls += ligcolp_g[(size_t)(b * NB1_ + s) * F_ + f];
    }
    zsm[q][f] = zs; lsm[q][f] = ls;
    __syncthreads();
    if (tid < 128) {
        float Zc  = zsm[0][tid] + zsm[1][tid];
        float lgc = lsm[0][tid] + lsm[1][tid];
        lco_sm[tid] = __fdividef(lgc * fg_mask[b * F_ + tid], Zc);
    }
    __syncthreads();
    float4 lco4 = ((const float4*)lco_sm)[t];

    // row loop: 8 warps x 4 rows, lane t owns f=4t..4t+3
    float4 Pa = make_float4(0.f, 0.f, 0.f, 0.f);
    float4 Ca = make_float4(0.f, 0.f, 0.f, 0.f);
    int rbase = blk * 32 + w * 4;
    #pragma unroll
    for (int i = 0; i < 4; i++) {
        int r = rbase + i;
        float ps = pscore_g[b * R_ + r];
        float pm = prot_mask[b * R_ + r];
        float mexr = __expf(-(1.0f - pm) * 1e9f);
        uint2 e2v = ((const uint2*)(E_h + (size_t)(b * R_ + r) * F_))[t];
        __half2 ha = *reinterpret_cast<__half2*>(&e2v.x);
        __half2 hb = *reinterpret_cast<__half2*>(&e2v.y);
        float2 fa = __half22float2(ha);
        float2 fb = __half22float2(hb);
        float dv = lco4.x * fa.x + lco4.y * fa.y + lco4.z * fb.x + lco4.w * fb.y;
        float craw = mexr * warpAllSum(dv);
        float4 P4 = ((const float4*)(protein_emb + (size_t)(b * R_ + r) * D_))[t];
        Pa.x = fmaf(ps, P4.x, Pa.x); Pa.y = fmaf(ps, P4.y, Pa.y);
        Pa.z = fmaf(ps, P4.z, Pa.z); Pa.w = fmaf(ps, P4.w, Pa.w);
        Ca.x = fmaf(craw, P4.x, Ca.x); Ca.y = fmaf(craw, P4.y, Ca.y);
        Ca.z = fmaf(craw, P4.z, Ca.z); Ca.w = fmaf(craw, P4.w, Ca.w);
    }

    __syncthreads();
    float4* st4 = (float4*)stage;
    st4[w * 32 + t]       = Pa;
    st4[256 + w * 32 + t] = Ca;
    __syncthreads();
    if (tid < 128) {
        float s = 0.0f;
        #pragma unroll
        for (int ww = 0; ww < 8; ww++) s += stage[ww * 128 + tid];
        Pwp_g[(size_t)(b * NB3_ + blk) * D_ + tid] = s;
    } else {
        float s = 0.0f;
        #pragma unroll
        for (int ww = 0; ww < 8; ww++) s += stage[1024 + ww * 128 + f];
        Cwp_g[(size_t)(b * NB3_ + blk) * D_ + f] = s;
    }
#if __CUDA_ARCH__ >= 900
    cudaTriggerProgrammaticLaunchCompletion();
#endif
}

// ============ KHEAD: 1024 threads — pools + feat + norm + MLP ==============
__global__ void __launch_bounds__(1024, 1) khead(const float* __restrict__ ligand_emb,
                        const float* __restrict__ fg_mask,
                        const float* __restrict__ Wr, const float* __restrict__ br,
                        const float* __restrict__ Wf, const float* __restrict__ bf,
                        const float* __restrict__ W1, const float* __restrict__ b1,
                        const float* __restrict__ W2, const float* __restrict__ b2,
                        const float* __restrict__ W3, const float* __restrict__ b3,
                        float* __restrict__ dout, int osz) {
    int b = blockIdx.x, tid = threadIdx.x, w = tid >> 5, t = tid & 31;
    int f = tid & 127, q = tid >> 7;     // q in 0..7

    __shared__ float red[32];
    __shared__ float big[3072];
    __shared__ float lw_sm[128], la_s[128];
    __shared__ float Pws[128], Cws[128];
    __shared__ float gs[128], Ls[128];
    __shared__ float feat[FEAT_ + 1];
    __shared__ float h1[H_], h2[H2_];
    __shared__ float tst[8];

    // PDL prolog
    if (b == 0) for (int i = B_ + B_ * FEAT_ + tid; i < osz; i += 1024) dout[i] = 0.0f;
#if __CUDA_ARCH__ >= 900
    cudaGridDependencySynchronize();
#endif

    // psum: exactly one pscore element per thread
    float v = pscore_g[b * R_ + tid];
    float psum = blockReduceSum(v, red);
    float ip = __fdividef(1.0f, psum + 1e-8f);
    float spw = psum * ip;

    // ligcol sums (32 slots; 8 groups of 4)
    {
        float ls = 0.0f;
        #pragma unroll
        for (int s = 0; s < 4; s++) ls += ligcolp_g[(size_t)(b * NB1_ + q * 4 + s) * F_ + f];
        big[q * 128 + f] = ls;
    }
    __syncthreads();
    float lw0 = 0.0f;
    if (tid < 128) {
        float lgc = 0.0f;
        #pragma unroll
        for (int j = 0; j < 8; j++) lgc += big[j * 128 + tid];
        lw0 = lgc * fg_mask[b * F_ + tid];
    }
    float lsum = blockReduceSum(lw0, red);
    float il = __fdividef(1.0f, lsum + 1e-8f);
    float slw = lsum * il;
    if (tid < 128) lw_sm[tid] = lw0 * il;

    // slot sums: abar/Pw/Cw (32 slots; 8 groups of 4)
    {
        float aA = 0.0f, aP = 0.0f, aC = 0.0f;
        #pragma unroll
        for (int s = 0; s < 4; s++) {
            int s1 = q * 4 + s;
            aA += abarp_g[(size_t)(b * NB1_ + s1) * F_ + f];
            aP += Pwp_g[(size_t)(b * NB3_ + s1) * D_ + f];
            aC += Cwp_g[(size_t)(b * NB3_ + s1) * D_ + f];
        }
        big[q * 128 + f]        = aA;
        big[1024 + q * 128 + f] = aP;
        big[2048 + q * 128 + f] = aC;
    }
    __syncthreads();
    if (tid < 128) {
        float aA = 0.0f, aP = 0.0f, aC = 0.0f;
        #pragma unroll
        for (int j = 0; j < 8; j++) {
            aA += big[j * 128 + tid];
            aP += big[1024 + j * 128 + tid];
            aC += big[2048 + j * 128 + tid];
        }
        float fg = fg_mask[b * F_ + tid];
        float mexf = __expf(-(1.0f - fg) * 1e9f);
        la_s[tid] = aA * mexf * ip;
        Pws[tid] = aP * ip;
        Cws[tid] = aC * il;
    }
    if (tid < K_) {
        float s = 0.0f;
        #pragma unroll
        for (int s2 = 0; s2 < NB1_; s2++) s += tstrp_g[(size_t)(b * NB1_ + s2) * 8 + tid];
        tst[tid] = s;
    }
    __syncthreads();

    // ligand pooling: 8 f-chunks x 128 d
    {
        float ag = 0.0f, aL = 0.0f;
        #pragma unroll
        for (int i = 0; i < 16; i++) {
            int ff = q * 16 + i;
            float lv = ligand_emb[(size_t)(b * F_ + ff) * D_ + f];
            ag += la_s[ff] * lv;
            aL += lw_sm[ff] * lv;
        }
        big[q * 128 + f] = ag;
        big[1024 + q * 128 + f] = aL;
    }
    __syncthreads();
    if (tid < 128) {
        float g = 0.0f, L = 0.0f;
        #pragma unroll
        for (int j = 0; j < 8; j++) { g += big[j * 128 + tid]; L += big[1024 + j * 128 + tid]; }
        gs[tid] = g; Ls[tid] = L;
    }
    __syncthreads();

    // feat rows: warps 0-15 -> Wr/gs, 16-31 -> Wf/Cws; 8 rows/warp, 4 per iter
    {
        const float* Wm = (w < 16) ? Wr : Wf;
        const float* vec = (w < 16) ? gs : Cws;
        int rb = (w & 15) * 8;
        #pragma unroll 1
        for (int i = 0; i < 2; i++) {
            int r0 = rb + i * 4;
            float p0=0.f,p1=0.f,p2=0.f,p3=0.f;
            #pragma unroll
            for (int u = 0; u < 4; u++) {
                int j = t + 32 * u;
                float g = vec[j];
                p0 += Wm[(r0+0)*D_ + j] * g;
                p1 += Wm[(r0+1)*D_ + j] * g;
                p2 += Wm[(r0+2)*D_ + j] * g;
                p3 += Wm[(r0+3)*D_ + j] * g;
            }
            p0 = warpSum(p0); p1 = warpSum(p1); p2 = warpSum(p2); p3 = warpSum(p3);
            if (t == 0) {
                if (w < 16) {
                    feat[r0+0] = Pws[r0+0] + p0 + spw * br[r0+0];
                    feat[r0+1] = Pws[r0+1] + p1 + spw * br[r0+1];
                    feat[r0+2] = Pws[r0+2] + p2 + spw * br[r0+2];
                    feat[r0+3] = Pws[r0+3] + p3 + spw * br[r0+3];
                } else {
                    feat[128+r0+0] = Ls[r0+0] + p0 + slw * bf[r0+0];
                    feat[128+r0+1] = Ls[r0+1] + p1 + slw * bf[r0+1];
                    feat[128+r0+2] = Ls[r0+2] + p2 + slw * bf[r0+2];
                    feat[128+r0+3] = Ls[r0+3] + p3 + slw * bf[r0+3];
                }
            }
        }
    }
    if (tid < K_) feat[2 * D_ + tid] = tst[tid];
    __syncthreads();

    // norm + normalized-feat output
    float sv = (tid < FEAT_) ? feat[tid] * feat[tid] : 0.0f;
    float nrm = blockReduceSum(sv, red);
    float inv = 1.0f / fmaxf(sqrtf(nrm), 1e-12f);
    if (tid < FEAT_) {
        int oi = B_ + b * FEAT_ + tid;
        if (oi < osz) dout[oi] = feat[tid] * inv;
    }

    // MLP layer 1: 512 rows, 16/warp, 4 per iteration
    {
        int rb = w * 16;
        #pragma unroll 1
        for (int i = 0; i < 4; i++) {
            int r0 = rb + i * 4;
            float p0=0.f,p1=0.f,p2=0.f,p3=0.f;
            #pragma unroll
            for (int u = 0; u < 8; u++) {
                int j = t + 32 * u;
                float fv = feat[j];
                p0 += W1[(r0+0)*FEAT_ + j] * fv;
                p1 += W1[(r0+1)*FEAT_ + j] * fv;
                p2 += W1[(r0+2)*FEAT_ + j] * fv;
                p3 += W1[(r0+3)*FEAT_ + j] * fv;
            }
            if (t < 7) {
                int j = 256 + t;
                float fv = feat[j];
                p0 += W1[(r0+0)*FEAT_ + j] * fv;
                p1 += W1[(r0+1)*FEAT_ + j] * fv;
                p2 += W1[(r0+2)*FEAT_ + j] * fv;
                p3 += W1[(r0+3)*FEAT_ + j] * fv;
            }
            p0 = warpSum(p0); p1 = warpSum(p1); p2 = warpSum(p2); p3 = warpSum(p3);
            if (t == 0) {
                h1[r0+0] = fmaxf(p0 + b1[r0+0], 0.0f);
                h1[r0+1] = fmaxf(p1 + b1[r0+1], 0.0f);
                h1[r0+2] = fmaxf(p2 + b1[r0+2], 0.0f);
                h1[r0+3] = fmaxf(p3 + b1[r0+3], 0.0f);
            }
        }
    }
    __syncthreads();

    // MLP layer 2: 256 rows, 8/warp, 2 per iteration
    {
        int rb = w * 8;
        #pragma unroll 1
        for (int i = 0; i < 4; i++) {
            int r0 = rb + i * 2;
            float p0=0.f,p1=0.f;
            #pragma unroll
            for (int u = 0; u < 16; u++) {
                int j = t + 32 * u;
                float hv = h1[j];
                p0 += W2[(r0+0)*H_ + j] * hv;
                p1 += W2[(r0+1)*H_ + j] * hv;
            }
            p0 = warpSum(p0); p1 = warpSum(p1);
            if (t == 0) {
                h2[r0+0] = fmaxf(p0 + b2[r0+0], 0.0f);
                h2[r0+1] = fmaxf(p1 + b2[r0+1], 0.0f);
            }
        }
    }
    __syncthreads();
    float pv = (tid < H2_) ? W3[tid] * h2[tid] : 0.0f;
    float pred = blockReduceSum(pv, red);
    if (tid == 0 && b < osz) dout[b] = pred + b3[0];
}

// ---------------- launch ----------------
extern "C" void kernel_launch(void* const* d_in, const int* in_sizes, int n_in,
                              void* d_out, int out_size) {
    const float* lig    = (const float*)d_in[0];
    const float* prot   = (const float*)d_in[1];
    const float* logits = (const float*)d_in[2];
    const float* fg     = (const float*)d_in[3];
    const float* pmsk   = (const float*)d_in[4];
    const float* tw     = (const float*)d_in[5];
    const float* Wr = (const float*)d_in[6];  const float* br = (const float*)d_in[7];
    const float* Wf = (const float*)d_in[8];  const float* bf = (const float*)d_in[9];
    const float* W1 = (const float*)d_in[10]; const float* b1 = (const float*)d_in[11];
    const float* W2 = (const float*)d_in[12]; const float* b2 = (const float*)d_in[13];
    const float* W3 = (const float*)d_in[14]; const float* b3 = (const float*)d_in[15];
    float* out = (float*)d_out;

    k1_logits<<<dim3(NB1_, B_), 256>>>(logits, fg, pmsk, tw);

    // k3 with PDL: overlaps its prefetch prolog with k1's tail
    {
        cudaLaunchConfig_t cfg = {};
        cfg.gridDim = dim3(NB3_, B_);
        cfg.blockDim = dim3(256, 1, 1);
        cfg.dynamicSmemBytes = 0;
        cfg.stream = 0;
        cudaLaunchAttribute attrs[1];
        attrs[0].id = cudaLaunchAttributeProgrammaticStreamSerialization;
        attrs[0].val.programmaticStreamSerializationAllowed = 1;
        cfg.attrs = attrs;
        cfg.numAttrs = 1;
        cudaLaunchKernelEx(&cfg, k3_epass, prot, lig, fg, pmsk, Wr, Wf, W1, W2);
    }

    // khead with PDL: overlaps dout tail-zero + launch latency with k3's tail
    {
        cudaLaunchConfig_t cfg = {};
        cfg.gridDim = dim3(B_, 1, 1);
        cfg.blockDim = dim3(1024, 1, 1);
        cfg.dynamicSmemBytes = 0;
        cfg.stream = 0;
        cudaLaunchAttribute attrs[1];
        attrs[0].id = cudaLaunchAttributeProgrammaticStreamSerialization;
        attrs[0].val.programmaticStreamSerializationAllowed = 1;
        cfg.attrs = attrs;
        cfg.numAttrs = 1;
        cudaLaunchKernelEx(&cfg, khead, lig, fg, Wr, br, Wf, bf,
                           W1, b1, W2, b2, W3, b3, out, out_size);
    }
}

// round 13
// speedup vs baseline: 1.1213x; 1.0008x over previous
#include <cuda_runtime.h>
#include <cuda_fp16.h>
#include <cstdint>
#include <math.h>

#define B_ 16
#define R_ 1024
#define F_ 128
#define D_ 128
#define K_ 7
#define H_ 512
#define H2_ 256
#define FEAT_ 263   // 2*D + K
#define NB1_ 32     // k1 blocks per batch (32 rows each)
#define NB3_ 32     // k3 blocks per batch (32 rows each)
#define K1_SMEM (8 * 2 * 896 * 4)   // 57344 B: per-warp double row buffers

// ---------------- device scratch (static, allocation-free) ----------------
__device__ __half E_h[B_ * R_ * F_];         // exp(masked S), fp16 (E in [1,3.74])
__device__ float Zrow_g[B_ * R_];            // sum_f E*mexf
__device__ float pscore_g[B_ * R_];          // S.sum(f) * pm
__device__ float Zcolp_g[B_ * NB1_ * F_];    // partial: sum_r E*mexr
__device__ float ligcolp_g[B_ * NB1_ * F_];  // partial: sum_r S
__device__ float abarp_g[B_ * NB1_ * F_];    // partial: sum_r coef_r*E
__device__ float tstrp_g[B_ * NB1_ * 8];     // partial type strength
__device__ float Pwp_g[B_ * NB3_ * D_];      // partial: sum_r pscore_r*P  (unscaled)
__device__ float Cwp_g[B_ * NB3_ * D_];      // partial: sum_r craw_r*P    (unscaled)

// ---------------- helpers ----------------
__device__ __forceinline__ float warpSum(float v) {
    #pragma unroll
    for (int o = 16; o > 0; o >>= 1) v += __shfl_down_sync(0xffffffffu, v, o);
    return v;
}
__device__ __forceinline__ float warpAllSum(float v) {
    #pragma unroll
    for (int o = 16; o > 0; o >>= 1) v += __shfl_xor_sync(0xffffffffu, v, o);
    return v;
}
__device__ __forceinline__ float blockReduceSum(float v, float* sm) {
    int lane = threadIdx.x & 31, w = threadIdx.x >> 5;
    int nw = (blockDim.x + 31) >> 5;
    v = warpSum(v);
    if (lane == 0) sm[w] = v;
    __syncthreads();
    float r = (threadIdx.x < nw) ? sm[threadIdx.x] : 0.0f;
    if (w == 0) r = warpSum(r);
    if (threadIdx.x == 0) sm[0] = r;
    __syncthreads();
    r = sm[0];
    __syncthreads();
    return r;
}
__device__ __forceinline__ void l2pf(const void* p) {
    asm volatile("prefetch.global.L2 [%0];" :: "l"(p));
}
__device__ __forceinline__ void cpasync16(unsigned int saddr, const void* gptr) {
    asm volatile("cp.async.cg.shared.global [%0], [%1], 16;" :: "r"(saddr), "l"(gptr));
}
__device__ __forceinline__ void cpasync_commit() {
    asm volatile("cp.async.commit_group;" ::: "memory");
}
template<int N>
__device__ __forceinline__ void cpasync_wait() {
    asm volatile("cp.async.wait_group %0;" :: "n"(N) : "memory");
}

// per-element softmax+weights macro (uses wshr, tk, rowS, rowE, mexr in scope)
#define ELEM(X0,X1,X2,X3,X4,X5,X6, PMF, MEXF, EOUT, ZC, LC) do {              \
    float e0_=__expf(X0), e1_=__expf(X1), e2_=__expf(X2), e3_=__expf(X3);      \
    float e4_=__expf(X4), e5_=__expf(X5), e6_=__expf(X6);                      \
    float s_ = ((e0_+e1_)+(e2_+e3_))+((e4_+e5_)+e6_);                          \
    float inv_ = __fdividef(1.0f, s_);                                         \
    float h_ = e0_*wshr[0]; h_=fmaf(e1_,wshr[1],h_); h_=fmaf(e2_,wshr[2],h_);  \
    h_=fmaf(e3_,wshr[3],h_); h_=fmaf(e4_,wshr[4],h_);                          \
    h_=fmaf(e5_,wshr[5],h_); h_=fmaf(e6_,wshr[6],h_);                          \
    tk[0]=fmaf(e0_,inv_,tk[0]); tk[1]=fmaf(e1_,inv_,tk[1]);                    \
    tk[2]=fmaf(e2_,inv_,tk[2]); tk[3]=fmaf(e3_,inv_,tk[3]);                    \
    tk[4]=fmaf(e4_,inv_,tk[4]); tk[5]=fmaf(e5_,inv_,tk[5]);                    \
    tk[6]=fmaf(e6_,inv_,tk[6]);                                                \
    float Sm_ = h_*inv_*(PMF);                                                 \
    float E_ = __expf(Sm_);                                                    \
    EOUT = E_; rowS += Sm_; rowE = fmaf(E_, (MEXF), rowE);                     \
    ZC = fmaf(E_, mexr, ZC); LC += Sm_;                                        \
} while(0)

// ====== K1: warp-private cp.async double-buffered staging, vectorized ======
__global__ void __launch_bounds__(256, 4) k1_logits(const float* __restrict__ logits,
                          const float* __restrict__ fg_mask,
                          const float* __restrict__ prot_mask,
                          const float* __restrict__ tw) {
    extern __shared__ __align__(16) float dbuf[];   // 8 warps x 2 x 896 floats
    int b = blockIdx.y, blk = blockIdx.x;
    int tid = threadIdx.x, w = tid >> 5, t = tid & 31;

    __shared__ float tks[8][8];
    __shared__ float wsh_s[8];

    if (tid < K_) {
        float x = tw[tid];
        wsh_s[tid] = fmaxf(x, 0.0f) + log1pf(expf(-fabsf(x)));
    }
    __syncthreads();
    float wshr[K_];
    #pragma unroll
    for (int k = 0; k < K_; k++) wshr[k] = wsh_s[k];

    float4 fg4 = ((const float4*)(fg_mask + b * F_))[t];
    float mexf0 = __expf(-(1.0f - fg4.x) * 1e9f);
    float mexf1 = __expf(-(1.0f - fg4.y) * 1e9f);
    float mexf2 = __expf(-(1.0f - fg4.z) * 1e9f);
    float mexf3 = __expf(-(1.0f - fg4.w) * 1e9f);

    float zc0=0.f,zc1=0.f,zc2=0.f,zc3=0.f;
    float lc0=0.f,lc1=0.f,lc2=0.f,lc3=0.f;
    float ab0=0.f,ab1=0.f,ab2=0.f,ab3=0.f;
    float tk[K_];
    #pragma unroll
    for (int k = 0; k < K_; k++) tk[k] = 0.0f;

    int r0 = blk * 32 + w * 4;
    float* wbuf = dbuf + w * 1792;                    // this warp's 2-row region
    unsigned int sb = (unsigned int)__cvta_generic_to_shared(wbuf);

    // stage row r into parity buffer p (7 x cp.async 16B per lane)
    const float* lbase = logits + (size_t)(b * R_) * 896;
    {   // prologue: row 0 -> buffer 0
        const float4* src = (const float4*)(lbase + (size_t)r0 * 896);
        #pragma unroll
        for (int j = 0; j < 7; j++) cpasync16(sb + (t + 32 * j) * 16, src + t + 32 * j);
        cpasync_commit();
    }

    for (int i = 0; i < 4; i++) {
        if (i < 3) {
            const float4* src = (const float4*)(lbase + (size_t)(r0 + i + 1) * 896);
            unsigned int sa = sb + ((i + 1) & 1) * 3584;
            #pragma unroll
            for (int j = 0; j < 7; j++) cpasync16(sa + (t + 32 * j) * 16, src + t + 32 * j);
            cpasync_commit();
            cpasync_wait<1>();
        } else {
            cpasync_wait<0>();
        }
        __syncwarp();

        int r = r0 + i;
        const float4* bp4 = (const float4*)(wbuf + (i & 1) * 896 + t * 28);
        float pm = prot_mask[b * R_ + r];
        float mexr = __expf(-(1.0f - pm) * 1e9f);
        float rowS = 0.0f, rowE = 0.0f;
        float E0, E1, E2, E3;

        {
            float4 v0 = bp4[0], v1 = bp4[1], v2 = bp4[2], v3 = bp4[3];
            ELEM(v0.x, v0.y, v0.z, v0.w, v1.x, v1.y, v1.z, pm * fg4.x, mexf0, E0, zc0, lc0);
            ELEM(v1.w, v2.x, v2.y, v2.z, v2.w, v3.x, v3.y, pm * fg4.y, mexf1, E1, zc1, lc1);
            float4 v4 = bp4[4], v5 = bp4[5], v6 = bp4[6];
            ELEM(v3.z, v3.w, v4.x, v4.y, v4.z, v4.w, v5.x, pm * fg4.z, mexf2, E2, zc2, lc2);
            ELEM(v5.y, v5.z, v5.w, v6.x, v6.y, v6.z, v6.w, pm * fg4.w, mexf3, E3, zc3, lc3);
        }

        {   // packed fp16 store: one STG.64
            __half2 ha = __halves2half2(__float2half_rn(E0), __float2half_rn(E1));
            __half2 hb = __halves2half2(__float2half_rn(E2), __float2half_rn(E3));
            uint2 pk;
            pk.x = *reinterpret_cast<unsigned int*>(&ha);
            pk.y = *reinterpret_cast<unsigned int*>(&hb);
            ((uint2*)(E_h + (size_t)(b * R_ + r) * F_))[t] = pk;
        }

        rowS = warpAllSum(rowS);
        rowE = warpAllSum(rowE);
        float ps = rowS * pm;
        if (t == 0) { pscore_g[b * R_ + r] = ps; Zrow_g[b * R_ + r] = rowE; }
        float coef = __fdividef(ps, rowE);
        ab0 = fmaf(coef, E0, ab0);
        ab1 = fmaf(coef, E1, ab1);
        ab2 = fmaf(coef, E2, ab2);
        ab3 = fmaf(coef, E3, ab3);
        __syncwarp();
    }

    // epilogue: block-wide reduction into deterministic partial slots
    #pragma unroll
    for (int k = 0; k < K_; k++) { float v = warpSum(tk[k]); if (t == 0) tks[w][k] = v; }
    __syncthreads();
    float4* bb4 = (float4*)dbuf;
    bb4[w * 32 + t]       = make_float4(zc0, zc1, zc2, zc3);
    bb4[256 + w * 32 + t] = make_float4(lc0, lc1, lc2, lc3);
    bb4[512 + w * 32 + t] = make_float4(ab0, ab1, ab2, ab3);
    __syncthreads();
    if (tid < 128) {
        float s = 0.0f, s2 = 0.0f, s3 = 0.0f;
        #pragma unroll
        for (int ww = 0; ww < 8; ww++) {
            s  += dbuf[ww * 128 + tid];
            s2 += dbuf[1024 + ww * 128 + tid];
            s3 += dbuf[2048 + ww * 128 + tid];
        }
        Zcolp_g[(size_t)(b * NB1_ + blk) * F_ + tid]   = s;
        ligcolp_g[(size_t)(b * NB1_ + blk) * F_ + tid] = s2;
        abarp_g[(size_t)(b * NB1_ + blk) * F_ + tid]   = s3;
    } else if (tid < 128 + K_) {
        int k = tid - 128;
        float s = 0.0f;
        #pragma unroll
        for (int ww = 0; ww < 8; ww++) s += tks[ww][k];
        tstrp_g[(size_t)(b * NB1_ + blk) * 8 + k] = s * wshr[k];
    }
#if __CUDA_ARCH__ >= 900
    cudaTriggerProgrammaticLaunchCompletion();
#endif
}

// ============ K3: vectorized E pass — craw + unscaled Pw/Cw partials =======
__global__ void __launch_bounds__(256, 6) k3_epass(const float* __restrict__ protein_emb,
                        const float* __restrict__ ligand_emb,
                        const float* __restrict__ fg_mask,
                        const float* __restrict__ prot_mask,
                        const float* __restrict__ Wr, const float* __restrict__ Wf,
                        const float* __restrict__ W1, const float* __restrict__ W2) {
    int b = blockIdx.y, blk = blockIdx.x;
    int tid = threadIdx.x, w = tid >> 5, t = tid & 31;
    int f = tid & 127, q = tid >> 7;

    __shared__ __align__(16) float lco_sm[128];
    __shared__ float zsm[2][128], lsm[2][128];
    __shared__ __align__(16) float stage[2048];

    // PDL prolog: L2 prefetch of head weights + ligand
    {
        int gb = b * NB3_ + blk;                       // 0..511
        long gid = (long)gb * 256 + tid;               // 0..131071
        const long n1 = 4208;
        const long n2 = 4096;
        const long nr = 512;
        const long nl = 8192;
        if (gid < n1)                      l2pf((const char*)W1 + gid * 128);
        else if (gid < n1+n2)              l2pf((const char*)W2 + (gid-n1) * 128);
        else if (gid < n1+n2+nr)           l2pf((const char*)Wr + (gid-n1-n2) * 128);
        else if (gid < n1+n2+2*nr)         l2pf((const char*)Wf + (gid-n1-n2-nr) * 128);
        else if (gid < n1+n2+2*nr+nl)      l2pf((const char*)ligand_emb + (gid-n1-n2-2*nr) * 128);
    }
#if __CUDA_ARCH__ >= 900
    cudaGridDependencySynchronize();
#endif

    // lcoef from k1 column partials
    float zs = 0.0f, ls = 0.0f;
    for (int s = q * 16; s < q * 16 + 16; s++) {
        zs += Zcolp_g[(size_t)(b * NB1_ + s) * F_ + f];
        ls += ligcolp_g[(size_t)(b * NB1_ + s) * F_ + f];
    }
    zsm[q][f] = zs; lsm[q][f] = ls;
    __syncthreads();
    if (tid < 128) {
        float Zc  = zsm[0][tid] + zsm[1][tid];
        float lgc = lsm[0][tid] + lsm[1][tid];
        lco_sm[tid] = __fdividef(lgc * fg_mask[b * F_ + tid], Zc);
    }
    __syncthreads();
    float4 lco4 = ((const float4*)lco_sm)[t];

    // row loop: 8 warps x 4 rows, lane t owns f=4t..4t+3
    float4 Pa = make_float4(0.f, 0.f, 0.f, 0.f);
    float4 Ca = make_float4(0.f, 0.f, 0.f, 0.f);
    int rbase = blk * 32 + w * 4;
    #pragma unroll
    for (int i = 0; i < 4; i++) {
        int r = rbase + i;
        float ps = pscore_g[b * R_ + r];
        float pm = prot_mask[b * R_ + r];
        float mexr = __expf(-(1.0f - pm) * 1e9f);
        uint2 e2v = ((const uint2*)(E_h + (size_t)(b * R_ + r) * F_))[t];
        __half2 ha = *reinterpret_cast<__half2*>(&e2v.x);
        __half2 hb = *reinterpret_cast<__half2*>(&e2v.y);
        float2 fa = __half22float2(ha);
        float2 fb = __half22float2(hb);
        float dv = lco4.x * fa.x + lco4.y * fa.y + lco4.z * fb.x + lco4.w * fb.y;
        float craw = mexr * warpAllSum(dv);
        float4 P4 = ((const float4*)(protein_emb + (size_t)(b * R_ + r) * D_))[t];
        Pa.x = fmaf(ps, P4.x, Pa.x); Pa.y = fmaf(ps, P4.y, Pa.y);
        Pa.z = fmaf(ps, P4.z, Pa.z); Pa.w = fmaf(ps, P4.w, Pa.w);
        Ca.x = fmaf(craw, P4.x, Ca.x); Ca.y = fmaf(craw, P4.y, Ca.y);
        Ca.z = fmaf(craw, P4.z, Ca.z); Ca.w = fmaf(craw, P4.w, Ca.w);
    }

    __syncthreads();
    float4* st4 = (float4*)stage;
    st4[w * 32 + t]       = Pa;
    st4[256 + w * 32 + t] = Ca;
    __syncthreads();
    if (tid < 128) {
        float s = 0.0f;
        #pragma unroll
        for (int ww = 0; ww < 8; ww++) s += stage[ww * 128 + tid];
        Pwp_g[(size_t)(b * NB3_ + blk) * D_ + tid] = s;
    } else {
        float s = 0.0f;
        #pragma unroll
        for (int ww = 0; ww < 8; ww++) s += stage[1024 + ww * 128 + f];
        Cwp_g[(size_t)(b * NB3_ + blk) * D_ + f] = s;
    }
#if __CUDA_ARCH__ >= 900
    cudaTriggerProgrammaticLaunchCompletion();
#endif
}

// ============ KHEAD: 1024 threads — pools + feat + norm + MLP ==============
__global__ void __launch_bounds__(1024, 1) khead(const float* __restrict__ ligand_emb,
                        const float* __restrict__ fg_mask,
                        const float* __restrict__ Wr, const float* __restrict__ br,
                        const float* __restrict__ Wf, const float* __restrict__ bf,
                        const float* __restrict__ W1, const float* __restrict__ b1,
                        const float* __restrict__ W2, const float* __restrict__ b2,
                        const float* __restrict__ W3, const float* __restrict__ b3,
                        float* __restrict__ dout, int osz) {
    int b = blockIdx.x, tid = threadIdx.x, w = tid >> 5, t = tid & 31;
    int f = tid & 127, q = tid >> 7;     // q in 0..7

    __shared__ float red[32];
    __shared__ float big[3072];
    __shared__ float lw_sm[128], la_s[128];
    __shared__ float Pws[128], Cws[128];
    __shared__ float gs[128], Ls[128];
    __shared__ float feat[FEAT_ + 1];
    __shared__ float h1[H_], h2[H2_];
    __shared__ float tst[8];

    // PDL prolog
    if (b == 0) for (int i = B_ + B_ * FEAT_ + tid; i < osz; i += 1024) dout[i] = 0.0f;
#if __CUDA_ARCH__ >= 900
    cudaGridDependencySynchronize();
#endif

    // psum
    float v = pscore_g[b * R_ + tid];
    float psum = blockReduceSum(v, red);
    float ip = __fdividef(1.0f, psum + 1e-8f);
    float spw = psum * ip;

    // ligcol sums (32 slots; 8 groups of 4)
    {
        float ls = 0.0f;
        #pragma unroll
        for (int s = 0; s < 4; s++) ls += ligcolp_g[(size_t)(b * NB1_ + q * 4 + s) * F_ + f];
        big[q * 128 + f] = ls;
    }
    __syncthreads();
    float lw0 = 0.0f;
    if (tid < 128) {
        float lgc = 0.0f;
        #pragma unroll
        for (int j = 0; j < 8; j++) lgc += big[j * 128 + tid];
        lw0 = lgc * fg_mask[b * F_ + tid];
    }
    float lsum = blockReduceSum(lw0, red);
    float il = __fdividef(1.0f, lsum + 1e-8f);
    float slw = lsum * il;
    if (tid < 128) lw_sm[tid] = lw0 * il;

    // slot sums: abar/Pw/Cw
    {
        float aA = 0.0f, aP = 0.0f, aC = 0.0f;
        #pragma unroll
        for (int s = 0; s < 4; s++) {
            int s1 = q * 4 + s;
            aA += abarp_g[(size_t)(b * NB1_ + s1) * F_ + f];
            aP += Pwp_g[(size_t)(b * NB3_ + s1) * D_ + f];
            aC += Cwp_g[(size_t)(b * NB3_ + s1) * D_ + f];
        }
        big[q * 128 + f]        = aA;
        big[1024 + q * 128 + f] = aP;
        big[2048 + q * 128 + f] = aC;
    }
    __syncthreads();
    if (tid < 128) {
        float aA = 0.0f, aP = 0.0f, aC = 0.0f;
        #pragma unroll
        for (int j = 0; j < 8; j++) {
            aA += big[j * 128 + tid];
            aP += big[1024 + j * 128 + tid];
            aC += big[2048 + j * 128 + tid];
        }
        float fg = fg_mask[b * F_ + tid];
        float mexf = __expf(-(1.0f - fg) * 1e9f);
        la_s[tid] = aA * mexf * ip;
        Pws[tid] = aP * ip;
        Cws[tid] = aC * il;
    }
    if (tid < K_) {
        float s = 0.0f;
        #pragma unroll
        for (int s2 = 0; s2 < NB1_; s2++) s += tstrp_g[(size_t)(b * NB1_ + s2) * 8 + tid];
        tst[tid] = s;
    }
    __syncthreads();

    // ligand pooling: 8 f-chunks x 128 d
    {
        float ag = 0.0f, aL = 0.0f;
        #pragma unroll
        for (int i = 0; i < 16; i++) {
            int ff = q * 16 + i;
            float lv = ligand_emb[(size_t)(b * F_ + ff) * D_ + f];
            ag += la_s[ff] * lv;
            aL += lw_sm[ff] * lv;
        }
        big[q * 128 + f] = ag;
        big[1024 + q * 128 + f] = aL;
    }
    __syncthreads();
    if (tid < 128) {
        float g = 0.0f, L = 0.0f;
        #pragma unroll
        for (int j = 0; j < 8; j++) { g += big[j * 128 + tid]; L += big[1024 + j * 128 + tid]; }
        gs[tid] = g; Ls[tid] = L;
    }
    __syncthreads();

    // feat rows
    {
        const float* Wm = (w < 16) ? Wr : Wf;
        const float* vec = (w < 16) ? gs : Cws;
        int rb = (w & 15) * 8;
        #pragma unroll 1
        for (int i = 0; i < 2; i++) {
            int r0 = rb + i * 4;
            float p0=0.f,p1=0.f,p2=0.f,p3=0.f;
            #pragma unroll
            for (int u = 0; u < 4; u++) {
                int j = t + 32 * u;
                float g = vec[j];
                p0 += Wm[(r0+0)*D_ + j] * g;
                p1 += Wm[(r0+1)*D_ + j] * g;
                p2 += Wm[(r0+2)*D_ + j] * g;
                p3 += Wm[(r0+3)*D_ + j] * g;
            }
            p0 = warpSum(p0); p1 = warpSum(p1); p2 = warpSum(p2); p3 = warpSum(p3);
            if (t == 0) {
                if (w < 16) {
                    feat[r0+0] = Pws[r0+0] + p0 + spw * br[r0+0];
                    feat[r0+1] = Pws[r0+1] + p1 + spw * br[r0+1];
                    feat[r0+2] = Pws[r0+2] + p2 + spw * br[r0+2];
                    feat[r0+3] = Pws[r0+3] + p3 + spw * br[r0+3];
                } else {
                    feat[128+r0+0] = Ls[r0+0] + p0 + slw * bf[r0+0];
                    feat[128+r0+1] = Ls[r0+1] + p1 + slw * bf[r0+1];
                    feat[128+r0+2] = Ls[r0+2] + p2 + slw * bf[r0+2];
                    feat[128+r0+3] = Ls[r0+3] + p3 + slw * bf[r0+3];
                }
            }
        }
    }
    if (tid < K_) feat[2 * D_ + tid] = tst[tid];
    __syncthreads();

    // norm + normalized-feat output
    float sv = (tid < FEAT_) ? feat[tid] * feat[tid] : 0.0f;
    float nrm = blockReduceSum(sv, red);
    float inv = 1.0f / fmaxf(sqrtf(nrm), 1e-12f);
    if (tid < FEAT_) {
        int oi = B_ + b * FEAT_ + tid;
        if (oi < osz) dout[oi] = feat[tid] * inv;
    }

    // MLP layer 1
    {
        int rb = w * 16;
        #pragma unroll 1
        for (int i = 0; i < 4; i++) {
            int r0 = rb + i * 4;
            float p0=0.f,p1=0.f,p2=0.f,p3=0.f;
            #pragma unroll
            for (int u = 0; u < 8; u++) {
                int j = t + 32 * u;
                float fv = feat[j];
                p0 += W1[(r0+0)*FEAT_ + j] * fv;
                p1 += W1[(r0+1)*FEAT_ + j] * fv;
                p2 += W1[(r0+2)*FEAT_ + j] * fv;
                p3 += W1[(r0+3)*FEAT_ + j] * fv;
            }
            if (t < 7) {
                int j = 256 + t;
                float fv = feat[j];
                p0 += W1[(r0+0)*FEAT_ + j] * fv;
                p1 += W1[(r0+1)*FEAT_ + j] * fv;
                p2 += W1[(r0+2)*FEAT_ + j] * fv;
                p3 += W1[(r0+3)*FEAT_ + j] * fv;
            }
            p0 = warpSum(p0); p1 = warpSum(p1); p2 = warpSum(p2); p3 = warpSum(p3);
            if (t == 0) {
                h1[r0+0] = fmaxf(p0 + b1[r0+0], 0.0f);
                h1[r0+1] = fmaxf(p1 + b1[r0+1], 0.0f);
                h1[r0+2] = fmaxf(p2 + b1[r0+2], 0.0f);
                h1[r0+3] = fmaxf(p3 + b1[r0+3], 0.0f);
            }
        }
    }
    __syncthreads();

    // MLP layer 2
    {
        int rb = w * 8;
        #pragma unroll 1
        for (int i = 0; i < 4; i++) {
            int r0 = rb + i * 2;
            float p0=0.f,p1=0.f;
            #pragma unroll
            for (int u = 0; u < 16; u++) {
                int j = t + 32 * u;
                float hv = h1[j];
                p0 += W2[(r0+0)*H_ + j] * hv;
                p1 += W2[(r0+1)*H_ + j] * hv;
            }
            p0 = warpSum(p0); p1 = warpSum(p1);
            if (t == 0) {
                h2[r0+0] = fmaxf(p0 + b2[r0+0], 0.0f);
                h2[r0+1] = fmaxf(p1 + b2[r0+1], 0.0f);
            }
        }
    }
    __syncthreads();
    float pv = (tid < H2_) ? W3[tid] * h2[tid] : 0.0f;
    float pred = blockReduceSum(pv, red);
    if (tid == 0 && b < osz) dout[b] = pred + b3[0];
}

// ---------------- launch ----------------
extern "C" void kernel_launch(void* const* d_in, const int* in_sizes, int n_in,
                              void* d_out, int out_size) {
    const float* lig    = (const float*)d_in[0];
    const float* prot   = (const float*)d_in[1];
    const float* logits = (const float*)d_in[2];
    const float* fg     = (const float*)d_in[3];
    const float* pmsk   = (const float*)d_in[4];
    const float* tw     = (const float*)d_in[5];
    const float* Wr = (const float*)d_in[6];  const float* br = (const float*)d_in[7];
    const float* Wf = (const float*)d_in[8];  const float* bf = (const float*)d_in[9];
    const float* W1 = (const float*)d_in[10]; const float* b1 = (const float*)d_in[11];
    const float* W2 = (const float*)d_in[12]; const float* b2 = (const float*)d_in[13];
    const float* W3 = (const float*)d_in[14]; const float* b3 = (const float*)d_in[15];
    float* out = (float*)d_out;

    static int smem_set = 0;
    if (!smem_set) {
        cudaFuncSetAttribute(k1_logits, cudaFuncAttributeMaxDynamicSharedMemorySize, K1_SMEM);
        smem_set = 1;
    }

    k1_logits<<<dim3(NB1_, B_), 256, K1_SMEM>>>(logits, fg, pmsk, tw);

    {
        cudaLaunchConfig_t cfg = {};
        cfg.gridDim = dim3(NB3_, B_);
        cfg.blockDim = dim3(256, 1, 1);
        cfg.dynamicSmemBytes = 0;
        cfg.stream = 0;
        cudaLaunchAttribute attrs[1];
        attrs[0].id = cudaLaunchAttributeProgrammaticStreamSerialization;
        attrs[0].val.programmaticStreamSerializationAllowed = 1;
        cfg.attrs = attrs;
        cfg.numAttrs = 1;
        cudaLaunchKernelEx(&cfg, k3_epass, prot, lig, fg, pmsk, Wr, Wf, W1, W2);
    }

    {
        cudaLaunchConfig_t cfg = {};
        cfg.gridDim = dim3(B_, 1, 1);
        cfg.blockDim = dim3(1024, 1, 1);
        cfg.dynamicSmemBytes = 0;
        cfg.stream = 0;
        cudaLaunchAttribute attrs[1];
        attrs[0].id = cudaLaunchAttributeProgrammaticStreamSerialization;
        attrs[0].val.programmaticStreamSerializationAllowed = 1;
        cfg.attrs = attrs;
        cfg.numAttrs = 1;
        cudaLaunchKernelEx(&cfg, khead, lig, fg, Wr, br, Wf, bf,
                           W1, b1, W2, b2, W3, b3, out, out_size);
    }
}